// round 1
// baseline (speedup 1.0000x reference)
#include <cuda_runtime.h>
#include <math.h>

// Problem shape (fixed by the reference)
#define BATCH 8
#define LSEQ  2048
#define DDIM  1024

// GEMM tiling
#define BM 128
#define BN 128
#define BK 16
#define TM 8
#define TN 8
#define NTHREADS 256
#define SPAD 4
#define SLD (BM + SPAD)   // 132 floats per smem row, 16B-aligned (132*4=528)

// Scratch: device globals (no allocation allowed in kernel_launch)
__device__ float g_proj[(size_t)BATCH * LSEQ * DDIM];      // 64 MB
__device__ float g_scores[(size_t)BATCH * LSEQ * LSEQ];    // 134 MB

struct SmemGemm {
    float As[2][BK][SLD];
    float Bs[2][BK][SLD];
};

__device__ __forceinline__ float4 ldg4(const float* __restrict__ p) {
    return *reinterpret_cast<const float4*>(p);
}

// Store an A/B(NT)-style float4 (4 consecutive k for one m/n row) transposed into smem
__device__ __forceinline__ void st_nt(SmemGemm* sm, float (*dst)[BK][SLD], int buf, int f, float4 v) {
    int m  = f >> 2;
    int kq = (f & 3) * 4;
    dst[buf][kq + 0][m] = v.x;
    dst[buf][kq + 1][m] = v.y;
    dst[buf][kq + 2][m] = v.z;
    dst[buf][kq + 3][m] = v.w;
}

// Mainloop: C += A(128xK tile rows) * B, both tiles end up as smem [k][m]/[k][n].
// BNT=true : B is K-major (rows = n, stride ldb over k)      -> "NT" gemm
// BNT=false: B is N-major (rows = k, stride ldb over n)      -> "NN" gemm (B tile loaded directly)
template <bool BNT>
__device__ __forceinline__ void run_gemm(SmemGemm* sm,
                                         const float* __restrict__ A,   // offset to block row, lda = lda
                                         const float* __restrict__ B,   // NT: offset to block n-row; NN: offset to block n-col
                                         int lda, int ldb, int K,
                                         float acc[TM][TN]) {
    const int tid = threadIdx.x;
    const int f0 = tid, f1 = tid + NTHREADS;
    const int nk = K / BK;

    // ---- prologue: tile 0 ----
    float4 a0 = ldg4(&A[(size_t)(f0 >> 2) * lda + (f0 & 3) * 4]);
    float4 a1 = ldg4(&A[(size_t)(f1 >> 2) * lda + (f1 & 3) * 4]);
    float4 b0, b1;
    if (BNT) {
        b0 = ldg4(&B[(size_t)(f0 >> 2) * ldb + (f0 & 3) * 4]);
        b1 = ldg4(&B[(size_t)(f1 >> 2) * ldb + (f1 & 3) * 4]);
    } else {
        b0 = ldg4(&B[(size_t)(f0 >> 5) * ldb + (f0 & 31) * 4]);
        b1 = ldg4(&B[(size_t)(f1 >> 5) * ldb + (f1 & 31) * 4]);
    }
    st_nt(sm, sm->As, 0, f0, a0);
    st_nt(sm, sm->As, 0, f1, a1);
    if (BNT) {
        st_nt(sm, sm->Bs, 0, f0, b0);
        st_nt(sm, sm->Bs, 0, f1, b1);
    } else {
        *reinterpret_cast<float4*>(&sm->Bs[0][f0 >> 5][(f0 & 31) * 4]) = b0;
        *reinterpret_cast<float4*>(&sm->Bs[0][f1 >> 5][(f1 & 31) * 4]) = b1;
    }
    __syncthreads();

    const int tx = tid & 15;
    const int ty = tid >> 4;

    int buf = 0;
    for (int kt = 0; kt < nk; kt++) {
        const bool more = (kt + 1) < nk;
        if (more) {
            const int k0 = (kt + 1) * BK;
            a0 = ldg4(&A[(size_t)(f0 >> 2) * lda + k0 + (f0 & 3) * 4]);
            a1 = ldg4(&A[(size_t)(f1 >> 2) * lda + k0 + (f1 & 3) * 4]);
            if (BNT) {
                b0 = ldg4(&B[(size_t)(f0 >> 2) * ldb + k0 + (f0 & 3) * 4]);
                b1 = ldg4(&B[(size_t)(f1 >> 2) * ldb + k0 + (f1 & 3) * 4]);
            } else {
                b0 = ldg4(&B[(size_t)(k0 + (f0 >> 5)) * ldb + (f0 & 31) * 4]);
                b1 = ldg4(&B[(size_t)(k0 + (f1 >> 5)) * ldb + (f1 & 31) * 4]);
            }
        }

        #pragma unroll
        for (int kk = 0; kk < BK; kk++) {
            float ar[TM], br[TN];
            *reinterpret_cast<float4*>(&ar[0]) = *reinterpret_cast<const float4*>(&sm->As[buf][kk][ty * TM]);
            *reinterpret_cast<float4*>(&ar[4]) = *reinterpret_cast<const float4*>(&sm->As[buf][kk][ty * TM + 4]);
            *reinterpret_cast<float4*>(&br[0]) = *reinterpret_cast<const float4*>(&sm->Bs[buf][kk][tx * TN]);
            *reinterpret_cast<float4*>(&br[4]) = *reinterpret_cast<const float4*>(&sm->Bs[buf][kk][tx * TN + 4]);
            #pragma unroll
            for (int i = 0; i < TM; i++)
                #pragma unroll
                for (int j = 0; j < TN; j++)
                    acc[i][j] = fmaf(ar[i], br[j], acc[i][j]);
        }

        if (more) {
            const int nb = buf ^ 1;
            st_nt(sm, sm->As, nb, f0, a0);
            st_nt(sm, sm->As, nb, f1, a1);
            if (BNT) {
                st_nt(sm, sm->Bs, nb, f0, b0);
                st_nt(sm, sm->Bs, nb, f1, b1);
            } else {
                *reinterpret_cast<float4*>(&sm->Bs[nb][f0 >> 5][(f0 & 31) * 4]) = b0;
                *reinterpret_cast<float4*>(&sm->Bs[nb][f1 >> 5][(f1 & 31) * 4]) = b1;
            }
            __syncthreads();
        }
        buf ^= 1;
    }
}

// ---------------------------------------------------------------------------
// Kernel 1: proj = relu(x @ W^T + b)   [B*L, D] x [D, D] -> g_proj
// ---------------------------------------------------------------------------
__global__ __launch_bounds__(NTHREADS) void proj_kernel(const float* __restrict__ x,
                                                        const float* __restrict__ W,
                                                        const float* __restrict__ bias) {
    __shared__ SmemGemm sm;
    float acc[TM][TN];
    #pragma unroll
    for (int i = 0; i < TM; i++)
        #pragma unroll
        for (int j = 0; j < TN; j++) acc[i][j] = 0.f;

    const int row0 = blockIdx.y * BM;
    const int col0 = blockIdx.x * BN;
    run_gemm<true>(&sm, x + (size_t)row0 * DDIM, W + (size_t)col0 * DDIM, DDIM, DDIM, DDIM, acc);

    const int tx = threadIdx.x & 15;
    const int ty = threadIdx.x >> 4;
    float bj[TN];
    #pragma unroll
    for (int j = 0; j < TN; j++) bj[j] = bias[col0 + tx * TN + j];

    #pragma unroll
    for (int i = 0; i < TM; i++) {
        const size_t r = (size_t)(row0 + ty * TM + i);
        float* op = &g_proj[r * DDIM + col0 + tx * TN];
        float4 o0, o1;
        o0.x = fmaxf(acc[i][0] + bj[0], 0.f);
        o0.y = fmaxf(acc[i][1] + bj[1], 0.f);
        o0.z = fmaxf(acc[i][2] + bj[2], 0.f);
        o0.w = fmaxf(acc[i][3] + bj[3], 0.f);
        o1.x = fmaxf(acc[i][4] + bj[4], 0.f);
        o1.y = fmaxf(acc[i][5] + bj[5], 0.f);
        o1.z = fmaxf(acc[i][6] + bj[6], 0.f);
        o1.w = fmaxf(acc[i][7] + bj[7], 0.f);
        reinterpret_cast<float4*>(op)[0] = o0;
        reinterpret_cast<float4*>(op)[1] = o1;
    }
}

// ---------------------------------------------------------------------------
// Kernel 2: scores[b] = proj[b] @ proj[b]^T, diag->0, masked cols -> -inf.
// Symmetric: only upper-triangular tile pairs computed; mirror written too.
// ---------------------------------------------------------------------------
__global__ __launch_bounds__(NTHREADS) void scores_kernel(const int* __restrict__ x_mask) {
    const int b = blockIdx.y;
    // map linear pair index -> (ti, tj) with ti <= tj over 16x16 tiles
    int p = blockIdx.x;
    int ti = 0;
    while (p >= (16 - ti)) { p -= (16 - ti); ti++; }
    const int tj = ti + p;

    __shared__ SmemGemm sm;
    float acc[TM][TN];
    #pragma unroll
    for (int i = 0; i < TM; i++)
        #pragma unroll
        for (int j = 0; j < TN; j++) acc[i][j] = 0.f;

    const float* Ab = g_proj + ((size_t)b * LSEQ + ti * BM) * DDIM;
    const float* Bb = g_proj + ((size_t)b * LSEQ + tj * BM) * DDIM;
    run_gemm<true>(&sm, Ab, Bb, DDIM, DDIM, DDIM, acc);

    const int tx = threadIdx.x & 15;
    const int ty = threadIdx.x >> 4;
    const int* mk = x_mask + (size_t)b * LSEQ;
    float* S = g_scores + (size_t)b * LSEQ * LSEQ;

    const int gi0 = ti * BM + ty * TM;
    const int gj0 = tj * BM + tx * TN;
    int mi[TM], mj[TN];
    #pragma unroll
    for (int i = 0; i < TM; i++) mi[i] = mk[gi0 + i];
    #pragma unroll
    for (int j = 0; j < TN; j++) mj[j] = mk[gj0 + j];

    const float NEGINF = -INFINITY;

    #pragma unroll
    for (int i = 0; i < TM; i++) {
        const int gi = gi0 + i;
        #pragma unroll
        for (int j = 0; j < TN; j++) {
            const int gj = gj0 + j;
            float v = acc[i][j];
            float o = mj[j] ? NEGINF : ((gi == gj) ? 0.f : v);
            S[(size_t)gi * LSEQ + gj] = o;
        }
    }
    if (ti != tj) {
        #pragma unroll
        for (int i = 0; i < TM; i++) {
            const int gi = gi0 + i;
            #pragma unroll
            for (int j = 0; j < TN; j++) {
                const int gj = gj0 + j;   // gi != gj guaranteed (different tiles)
                float o = mi[i] ? NEGINF : acc[i][j];
                S[(size_t)gj * LSEQ + gi] = o;
            }
        }
    }
}

// ---------------------------------------------------------------------------
// Kernel 3: row-wise softmax over the key dim (in place), one block per row
// ---------------------------------------------------------------------------
__global__ __launch_bounds__(NTHREADS) void softmax_kernel() {
    const size_t row = blockIdx.x;
    float* p = g_scores + row * LSEQ;
    const int t = threadIdx.x;

    float4 v0 = reinterpret_cast<const float4*>(p)[t * 2];
    float4 v1 = reinterpret_cast<const float4*>(p)[t * 2 + 1];

    float m = v0.x;
    m = fmaxf(m, v0.y); m = fmaxf(m, v0.z); m = fmaxf(m, v0.w);
    m = fmaxf(m, v1.x); m = fmaxf(m, v1.y); m = fmaxf(m, v1.z); m = fmaxf(m, v1.w);

    __shared__ float red[8];
    #pragma unroll
    for (int off = 16; off > 0; off >>= 1)
        m = fmaxf(m, __shfl_xor_sync(0xffffffffu, m, off));
    if ((t & 31) == 0) red[t >> 5] = m;
    __syncthreads();
    if (t == 0) {
        float mm = red[0];
        #pragma unroll
        for (int w = 1; w < 8; w++) mm = fmaxf(mm, red[w]);
        red[0] = mm;
    }
    __syncthreads();
    m = red[0];
    __syncthreads();

    float e[8];
    e[0] = expf(v0.x - m); e[1] = expf(v0.y - m); e[2] = expf(v0.z - m); e[3] = expf(v0.w - m);
    e[4] = expf(v1.x - m); e[5] = expf(v1.y - m); e[6] = expf(v1.z - m); e[7] = expf(v1.w - m);
    float s = e[0] + e[1] + e[2] + e[3] + e[4] + e[5] + e[6] + e[7];
    #pragma unroll
    for (int off = 16; off > 0; off >>= 1)
        s += __shfl_xor_sync(0xffffffffu, s, off);
    if ((t & 31) == 0) red[t >> 5] = s;
    __syncthreads();
    if (t == 0) {
        float ss = 0.f;
        #pragma unroll
        for (int w = 0; w < 8; w++) ss += red[w];
        red[0] = ss;
    }
    __syncthreads();
    const float inv = 1.0f / red[0];

    float4 o0, o1;
    o0.x = e[0] * inv; o0.y = e[1] * inv; o0.z = e[2] * inv; o0.w = e[3] * inv;
    o1.x = e[4] * inv; o1.y = e[5] * inv; o1.z = e[6] * inv; o1.w = e[7] * inv;
    reinterpret_cast<float4*>(p)[t * 2]     = o0;
    reinterpret_cast<float4*>(p)[t * 2 + 1] = o1;
}

// ---------------------------------------------------------------------------
// Kernel 4: out[b] = alpha[b] @ x[b]   (NN gemm, K = LSEQ)
// ---------------------------------------------------------------------------
__global__ __launch_bounds__(NTHREADS) void av_kernel(const float* __restrict__ x,
                                                      float* __restrict__ out) {
    const int b = blockIdx.z;
    const int m0 = blockIdx.y * BM;
    const int n0 = blockIdx.x * BN;

    __shared__ SmemGemm sm;
    float acc[TM][TN];
    #pragma unroll
    for (int i = 0; i < TM; i++)
        #pragma unroll
        for (int j = 0; j < TN; j++) acc[i][j] = 0.f;

    const float* A = g_scores + ((size_t)b * LSEQ + m0) * LSEQ;
    const float* Bm = x + (size_t)b * LSEQ * DDIM + n0;
    run_gemm<false>(&sm, A, Bm, LSEQ, DDIM, LSEQ, acc);

    const int tx = threadIdx.x & 15;
    const int ty = threadIdx.x >> 4;

    #pragma unroll
    for (int i = 0; i < TM; i++) {
        const size_t r = (size_t)b * LSEQ + m0 + ty * TM + i;
        float* op = out + r * DDIM + n0 + tx * TN;
        float4 o0, o1;
        o0.x = acc[i][0]; o0.y = acc[i][1]; o0.z = acc[i][2]; o0.w = acc[i][3];
        o1.x = acc[i][4]; o1.y = acc[i][5]; o1.z = acc[i][6]; o1.w = acc[i][7];
        reinterpret_cast<float4*>(op)[0] = o0;
        reinterpret_cast<float4*>(op)[1] = o1;
    }
}

// ---------------------------------------------------------------------------
extern "C" void kernel_launch(void* const* d_in, const int* in_sizes, int n_in,
                              void* d_out, int out_size) {
    const float* x      = (const float*)d_in[0];   // [8, 2048, 1024] f32
    const int*   x_mask = (const int*)d_in[1];     // [8, 2048] i32
    const float* W      = (const float*)d_in[2];   // [1024, 1024] f32
    const float* bias   = (const float*)d_in[3];   // [1024] f32
    float* out = (float*)d_out;                    // [8, 2048, 1024] f32

    proj_kernel<<<dim3(DDIM / BN, (BATCH * LSEQ) / BM), NTHREADS>>>(x, W, bias);
    scores_kernel<<<dim3(136, BATCH), NTHREADS>>>(x_mask);
    softmax_kernel<<<BATCH * LSEQ, NTHREADS>>>();
    av_kernel<<<dim3(DDIM / BN, LSEQ / BM, BATCH), NTHREADS>>>(x, out);
}

// round 3
// speedup vs baseline: 2.0498x; 2.0498x over previous
#include <cuda_runtime.h>
#include <cuda_bf16.h>
#include <stdint.h>
#include <math.h>

#define BATCH 8
#define LSEQ  2048
#define DDIM  1024

typedef __nv_bfloat16 bf16;

// ---------------------------------------------------------------------------
// Scratch (device globals: no allocation allowed)
// ---------------------------------------------------------------------------
__device__ float g_scores[(size_t)BATCH * LSEQ * LSEQ];            // 134 MB
__device__ bf16  g_xh [(size_t)BATCH * LSEQ * DDIM];
__device__ bf16  g_xl [(size_t)BATCH * LSEQ * DDIM];
__device__ bf16  g_xth[(size_t)BATCH * DDIM * LSEQ];
__device__ bf16  g_xtl[(size_t)BATCH * DDIM * LSEQ];
__device__ bf16  g_wh [(size_t)DDIM * DDIM];
__device__ bf16  g_wl [(size_t)DDIM * DDIM];
__device__ bf16  g_ph [(size_t)BATCH * LSEQ * DDIM];
__device__ bf16  g_pl [(size_t)BATCH * LSEQ * DDIM];
__device__ bf16  g_ah [(size_t)BATCH * LSEQ * LSEQ];
__device__ bf16  g_al [(size_t)BATCH * LSEQ * LSEQ];

// ---------------------------------------------------------------------------
// PTX helpers (base sm_103 target — NO tcgen05, all sm_80+ instructions)
// ---------------------------------------------------------------------------
__device__ __forceinline__ uint32_t smem_u32(const void* p) {
    uint32_t a;
    asm("{ .reg .u64 t; cvta.to.shared.u64 t, %1; cvt.u32.u64 %0, t; }" : "=r"(a) : "l"(p));
    return a;
}

__device__ __forceinline__ void cpa16(uint32_t d, const void* s) {
    asm volatile("cp.async.cg.shared.global [%0], [%1], 16;" :: "r"(d), "l"(s) : "memory");
}

#define CP_COMMIT() asm volatile("cp.async.commit_group;" ::: "memory")
#define CP_WAIT2()  asm volatile("cp.async.wait_group 2;" ::: "memory")

#define LDSM4(r, addr) \
    asm volatile("ldmatrix.sync.aligned.m8n8.x4.shared.b16 {%0,%1,%2,%3}, [%4];" \
        : "=r"((r)[0]), "=r"((r)[1]), "=r"((r)[2]), "=r"((r)[3]) : "r"(addr))

#define MMA(d, a, b0, b1) \
    asm volatile("mma.sync.aligned.m16n8k16.row.col.f32.bf16.bf16.f32 " \
        "{%0,%1,%2,%3}, {%4,%5,%6,%7}, {%8,%9}, {%0,%1,%2,%3};" \
        : "+f"((d)[0]), "+f"((d)[1]), "+f"((d)[2]), "+f"((d)[3]) \
        : "r"((a)[0]), "r"((a)[1]), "r"((a)[2]), "r"((a)[3]), "r"(b0), "r"(b1))

// ---------------------------------------------------------------------------
// GEMM core: C(128x128 fp32) = sum_k (Ah+Al)(Bh+Bl)^T via 3-pass bf16 HMMA.
// A, B sources are k-contiguous (NT). BK=32. Smem stage (32KB):
//   A tile at +0:     128 rows x 128B  (row = [hi k0..31 | lo k0..31], XOR-swizzled)
//   B tile at +16384: same layout, rows = n index.
// 4 stages, cp.async pipeline. 256 threads, 8 warps (2x4), warp tile 64x32.
// ---------------------------------------------------------------------------
#define NSTAGE 4
#define STG    32768
#define SMEM_BYTES (NSTAGE * STG)

__device__ __forceinline__ void issue_stage(uint32_t sb, int s, int tid,
    const bf16* __restrict__ Ah, const bf16* __restrict__ Al, size_t lda,
    const bf16* __restrict__ Bh, const bf16* __restrict__ Bl, size_t ldb, int kc)
{
    const uint32_t base = sb + (uint32_t)(s & 3) * STG;
    #pragma unroll
    for (int j = 0; j < 4; j++) {
        const int q   = tid + j * 256;       // 0..1023
        const int row = q >> 3;
        const int c   = q & 7;               // chunk: 0-3 hi, 4-7 lo
        const uint32_t off = (uint32_t)(row * 128) + ((uint32_t)(c ^ (row & 7)) << 4);
        const bf16* sa = (c < 4) ? Ah + (size_t)row * lda + kc + c * 8
                                 : Al + (size_t)row * lda + kc + (c - 4) * 8;
        const bf16* sbp = (c < 4) ? Bh + (size_t)row * ldb + kc + c * 8
                                  : Bl + (size_t)row * ldb + kc + (c - 4) * 8;
        cpa16(base + off, sa);
        cpa16(base + 16384 + off, sbp);
    }
    CP_COMMIT();
}

__device__ __forceinline__ void compute_stage(uint32_t base, int m0, int n0, int lane,
                                              float acc[4][4][4])
{
    const int rA = lane & 15, cA = lane >> 4;
    const int rB = (lane & 7) + ((lane >> 4) << 3), cB = (lane >> 3) & 1;

    #pragma unroll
    for (int kk = 0; kk < 2; kk++) {
        const int cb = kk * 2;               // hi chunks cb, cb+1 ; lo at +4
        uint32_t aH[4][4], aL[4][4], bH[2][4], bL[2][4];

        #pragma unroll
        for (int mt = 0; mt < 4; mt++) {
            const uint32_t rowb = base + (uint32_t)((m0 + mt * 16 + rA) * 128);
            LDSM4(aH[mt], rowb + ((uint32_t)((cb + cA)     ^ (rA & 7)) << 4));
            LDSM4(aL[mt], rowb + ((uint32_t)((cb + 4 + cA) ^ (rA & 7)) << 4));
        }
        #pragma unroll
        for (int nt2 = 0; nt2 < 2; nt2++) {
            const uint32_t rowb = base + 16384 + (uint32_t)((n0 + nt2 * 16 + rB) * 128);
            LDSM4(bH[nt2], rowb + ((uint32_t)((cb + cB)     ^ (rB & 7)) << 4));
            LDSM4(bL[nt2], rowb + ((uint32_t)((cb + 4 + cB) ^ (rB & 7)) << 4));
        }
        #pragma unroll
        for (int mt = 0; mt < 4; mt++)
            #pragma unroll
            for (int nt = 0; nt < 4; nt++) {
                const int g = nt >> 1, o = (nt & 1) * 2;
                MMA(acc[mt][nt], aH[mt], bH[g][o], bH[g][o + 1]);  // hi*hi
                MMA(acc[mt][nt], aH[mt], bL[g][o], bL[g][o + 1]);  // hi*lo
                MMA(acc[mt][nt], aL[mt], bH[g][o], bH[g][o + 1]);  // lo*hi
            }
    }
}

__device__ __forceinline__ void run_gemm(uint32_t sb, int tid,
    const bf16* __restrict__ Ah, const bf16* __restrict__ Al, size_t lda,
    const bf16* __restrict__ Bh, const bf16* __restrict__ Bl, size_t ldb, int nk,
    float acc[4][4][4])
{
    #pragma unroll
    for (int mt = 0; mt < 4; mt++)
        #pragma unroll
        for (int nt = 0; nt < 4; nt++)
            #pragma unroll
            for (int i = 0; i < 4; i++) acc[mt][nt][i] = 0.f;

    issue_stage(sb, 0, tid, Ah, Al, lda, Bh, Bl, ldb, 0);
    issue_stage(sb, 1, tid, Ah, Al, lda, Bh, Bl, ldb, 32);
    issue_stage(sb, 2, tid, Ah, Al, lda, Bh, Bl, ldb, 64);

    const int wid = tid >> 5, lane = tid & 31;
    const int m0 = (wid & 1) * 64, n0 = (wid >> 1) * 32;

    for (int kt = 0; kt < nk; kt++) {
        CP_WAIT2();
        __syncthreads();
        if (kt + NSTAGE - 1 < nk)
            issue_stage(sb, kt + 3, tid, Ah, Al, lda, Bh, Bl, ldb, (kt + 3) * 32);
        else
            CP_COMMIT();
        compute_stage(sb + (uint32_t)(kt & 3) * STG, m0, n0, lane, acc);
    }
}

__device__ __forceinline__ uint32_t packbf(float a, float b) {
    __nv_bfloat162 t = __floats2bfloat162_rn(a, b);
    return *reinterpret_cast<uint32_t*>(&t);
}

// ---------------------------------------------------------------------------
// GEMM 1: proj = relu(x @ W^T + b) -> split bf16
// ---------------------------------------------------------------------------
__global__ __launch_bounds__(256, 1) void proj_gemm(const float* __restrict__ bias) {
    extern __shared__ char smem[];
    const uint32_t sb = smem_u32(smem);
    const int tid = threadIdx.x;
    const int mblk = blockIdx.y * 128, nblk = blockIdx.x * 128;

    float acc[4][4][4];
    run_gemm(sb, tid,
             g_xh + (size_t)mblk * DDIM, g_xl + (size_t)mblk * DDIM, DDIM,
             g_wh + (size_t)nblk * DDIM, g_wl + (size_t)nblk * DDIM, DDIM,
             DDIM / 32, acc);

    const int wid = tid >> 5, lane = tid & 31;
    const int m0 = (wid & 1) * 64, n0 = (wid >> 1) * 32;
    const int quad = lane >> 2, tq = lane & 3;

    #pragma unroll
    for (int mt = 0; mt < 4; mt++)
        #pragma unroll
        for (int nt = 0; nt < 4; nt++) {
            const int col = nblk + n0 + nt * 8 + tq * 2;
            const float b0 = bias[col], b1 = bias[col + 1];
            #pragma unroll
            for (int h = 0; h < 2; h++) {
                const int row = mblk + m0 + mt * 16 + quad + h * 8;
                float v0 = fmaxf(acc[mt][nt][h * 2 + 0] + b0, 0.f);
                float v1 = fmaxf(acc[mt][nt][h * 2 + 1] + b1, 0.f);
                bf16 h0 = __float2bfloat16(v0), h1 = __float2bfloat16(v1);
                float l0 = v0 - __bfloat162float(h0), l1 = v1 - __bfloat162float(h1);
                *reinterpret_cast<uint32_t*>(g_ph + (size_t)row * DDIM + col) =
                    packbf(__bfloat162float(h0), __bfloat162float(h1));
                *reinterpret_cast<uint32_t*>(g_pl + (size_t)row * DDIM + col) =
                    packbf(l0, l1);
            }
        }
}

// ---------------------------------------------------------------------------
// GEMM 2: scores = proj @ proj^T, diag->0, masked key -> -inf (fp32)
// ---------------------------------------------------------------------------
__global__ __launch_bounds__(256, 1) void scores_gemm(const int* __restrict__ x_mask) {
    extern __shared__ char smem[];
    const uint32_t sb = smem_u32(smem);
    const int tid = threadIdx.x;
    const int b = blockIdx.z, ti = blockIdx.y, tj = blockIdx.x;
    const size_t pb = (size_t)b * LSEQ * DDIM;

    float acc[4][4][4];
    run_gemm(sb, tid,
             g_ph + pb + (size_t)ti * 128 * DDIM, g_pl + pb + (size_t)ti * 128 * DDIM, DDIM,
             g_ph + pb + (size_t)tj * 128 * DDIM, g_pl + pb + (size_t)tj * 128 * DDIM, DDIM,
             DDIM / 32, acc);

    const int wid = tid >> 5, lane = tid & 31;
    const int m0 = (wid & 1) * 64, n0 = (wid >> 1) * 32;
    const int quad = lane >> 2, tq = lane & 3;
    const int* mk = x_mask + (size_t)b * LSEQ;
    float* S = g_scores + (size_t)b * LSEQ * LSEQ;
    const float NEGINF = -INFINITY;

    #pragma unroll
    for (int nt = 0; nt < 4; nt++) {
        const int gj = tj * 128 + n0 + nt * 8 + tq * 2;
        const int mj0 = mk[gj], mj1 = mk[gj + 1];
        #pragma unroll
        for (int mt = 0; mt < 4; mt++)
            #pragma unroll
            for (int h = 0; h < 2; h++) {
                const int gi = ti * 128 + m0 + mt * 16 + quad + h * 8;
                float v0 = acc[mt][nt][h * 2 + 0];
                float v1 = acc[mt][nt][h * 2 + 1];
                v0 = (gi == gj)     ? 0.f : v0;
                v1 = (gi == gj + 1) ? 0.f : v1;
                float2 o;
                o.x = mj0 ? NEGINF : v0;
                o.y = mj1 ? NEGINF : v1;
                *reinterpret_cast<float2*>(S + (size_t)gi * LSEQ + gj) = o;
            }
    }
}

// ---------------------------------------------------------------------------
// GEMM 3: out = alpha @ x   (A = alpha split, B = x^T split)
// ---------------------------------------------------------------------------
__global__ __launch_bounds__(256, 1) void av_gemm(float* __restrict__ out) {
    extern __shared__ char smem[];
    const uint32_t sb = smem_u32(smem);
    const int tid = threadIdx.x;
    const int b = blockIdx.z;
    const int mblk = blockIdx.y * 128, nblk = blockIdx.x * 128;

    float acc[4][4][4];
    run_gemm(sb, tid,
             g_ah + ((size_t)b * LSEQ + mblk) * LSEQ, g_al + ((size_t)b * LSEQ + mblk) * LSEQ, LSEQ,
             g_xth + ((size_t)b * DDIM + nblk) * LSEQ, g_xtl + ((size_t)b * DDIM + nblk) * LSEQ, LSEQ,
             LSEQ / 32, acc);

    const int wid = tid >> 5, lane = tid & 31;
    const int m0 = (wid & 1) * 64, n0 = (wid >> 1) * 32;
    const int quad = lane >> 2, tq = lane & 3;

    #pragma unroll
    for (int mt = 0; mt < 4; mt++)
        #pragma unroll
        for (int nt = 0; nt < 4; nt++) {
            const int col = nblk + n0 + nt * 8 + tq * 2;
            #pragma unroll
            for (int h = 0; h < 2; h++) {
                const int row = mblk + m0 + mt * 16 + quad + h * 8;
                float2 o;
                o.x = acc[mt][nt][h * 2 + 0];
                o.y = acc[mt][nt][h * 2 + 1];
                *reinterpret_cast<float2*>(out + ((size_t)b * LSEQ + row) * DDIM + col) = o;
            }
        }
}

// ---------------------------------------------------------------------------
// Softmax over keys (fp32 scores in, split-bf16 alpha out)
// ---------------------------------------------------------------------------
__global__ __launch_bounds__(256) void softmax_kernel() {
    const size_t row = blockIdx.x;
    const float* p = g_scores + row * LSEQ;
    const int t = threadIdx.x;

    float4 v0 = reinterpret_cast<const float4*>(p)[t * 2];
    float4 v1 = reinterpret_cast<const float4*>(p)[t * 2 + 1];

    float m = fmaxf(fmaxf(fmaxf(v0.x, v0.y), fmaxf(v0.z, v0.w)),
                    fmaxf(fmaxf(v1.x, v1.y), fmaxf(v1.z, v1.w)));

    __shared__ float red[8];
    #pragma unroll
    for (int off = 16; off > 0; off >>= 1)
        m = fmaxf(m, __shfl_xor_sync(0xffffffffu, m, off));
    if ((t & 31) == 0) red[t >> 5] = m;
    __syncthreads();
    if (t == 0) {
        float mm = red[0];
        #pragma unroll
        for (int w = 1; w < 8; w++) mm = fmaxf(mm, red[w]);
        red[0] = mm;
    }
    __syncthreads();
    m = red[0];
    __syncthreads();

    float e[8];
    e[0] = expf(v0.x - m); e[1] = expf(v0.y - m); e[2] = expf(v0.z - m); e[3] = expf(v0.w - m);
    e[4] = expf(v1.x - m); e[5] = expf(v1.y - m); e[6] = expf(v1.z - m); e[7] = expf(v1.w - m);
    float s = e[0] + e[1] + e[2] + e[3] + e[4] + e[5] + e[6] + e[7];
    #pragma unroll
    for (int off = 16; off > 0; off >>= 1)
        s += __shfl_xor_sync(0xffffffffu, s, off);
    if ((t & 31) == 0) red[t >> 5] = s;
    __syncthreads();
    if (t == 0) {
        float ss = 0.f;
        #pragma unroll
        for (int w = 0; w < 8; w++) ss += red[w];
        red[0] = ss;
    }
    __syncthreads();
    const float inv = 1.0f / red[0];

    uint32_t hh[4], ll[4];
    #pragma unroll
    for (int i = 0; i < 4; i++) {
        float a0 = e[2 * i] * inv, a1 = e[2 * i + 1] * inv;
        bf16 h0 = __float2bfloat16(a0), h1 = __float2bfloat16(a1);
        hh[i] = packbf(__bfloat162float(h0), __bfloat162float(h1));
        ll[i] = packbf(a0 - __bfloat162float(h0), a1 - __bfloat162float(h1));
    }
    *reinterpret_cast<uint4*>(g_ah + row * LSEQ + t * 8) = *reinterpret_cast<uint4*>(hh);
    *reinterpret_cast<uint4*>(g_al + row * LSEQ + t * 8) = *reinterpret_cast<uint4*>(ll);
}

// ---------------------------------------------------------------------------
// fp32 -> split-bf16 conversions
// ---------------------------------------------------------------------------
__global__ __launch_bounds__(256) void split_kernel(const float* __restrict__ s,
                                                    bf16* __restrict__ hi,
                                                    bf16* __restrict__ lo, int n4) {
    const int i = blockIdx.x * 256 + threadIdx.x;
    if (i >= n4) return;
    float4 v = reinterpret_cast<const float4*>(s)[i];
    bf16 h0 = __float2bfloat16(v.x), h1 = __float2bfloat16(v.y);
    bf16 h2 = __float2bfloat16(v.z), h3 = __float2bfloat16(v.w);
    uint2 uh, ul;
    uh.x = packbf(__bfloat162float(h0), __bfloat162float(h1));
    uh.y = packbf(__bfloat162float(h2), __bfloat162float(h3));
    ul.x = packbf(v.x - __bfloat162float(h0), v.y - __bfloat162float(h1));
    ul.y = packbf(v.z - __bfloat162float(h2), v.w - __bfloat162float(h3));
    reinterpret_cast<uint2*>(hi)[i] = uh;
    reinterpret_cast<uint2*>(lo)[i] = ul;
}

// x[b][l][d] -> xt[b][d][l], split bf16
__global__ __launch_bounds__(256) void transpose_split_kernel(const float* __restrict__ x) {
    __shared__ float t[32][33];
    const int b = blockIdx.z, d0 = blockIdx.x * 32, l0 = blockIdx.y * 32;
    const int tx = threadIdx.x & 31, ty = threadIdx.x >> 5;   // 32 x 8
    const float* xb = x + (size_t)b * LSEQ * DDIM;
    #pragma unroll
    for (int j = 0; j < 4; j++)
        t[ty + j * 8][tx] = xb[(size_t)(l0 + ty + j * 8) * DDIM + d0 + tx];
    __syncthreads();
    bf16* oh = g_xth + (size_t)b * DDIM * LSEQ;
    bf16* ol = g_xtl + (size_t)b * DDIM * LSEQ;
    #pragma unroll
    for (int j = 0; j < 4; j++) {
        float v = t[tx][ty + j * 8];
        bf16 h = __float2bfloat16(v);
        float lo = v - __bfloat162float(h);
        const size_t o = (size_t)(d0 + ty + j * 8) * LSEQ + l0 + tx;
        oh[o] = h;
        ol[o] = __float2bfloat16(lo);
    }
}

// ---------------------------------------------------------------------------
extern "C" void kernel_launch(void* const* d_in, const int* in_sizes, int n_in,
                              void* d_out, int out_size) {
    const float* x      = (const float*)d_in[0];   // [8, 2048, 1024]
    const int*   x_mask = (const int*)d_in[1];     // [8, 2048]
    const float* W      = (const float*)d_in[2];   // [1024, 1024]
    const float* bias   = (const float*)d_in[3];   // [1024]
    float* out = (float*)d_out;                    // [8, 2048, 1024]

    cudaFuncSetAttribute(proj_gemm,   cudaFuncAttributeMaxDynamicSharedMemorySize, SMEM_BYTES);
    cudaFuncSetAttribute(scores_gemm, cudaFuncAttributeMaxDynamicSharedMemorySize, SMEM_BYTES);
    cudaFuncSetAttribute(av_gemm,     cudaFuncAttributeMaxDynamicSharedMemorySize, SMEM_BYTES);

    bf16 *xh, *xl, *wh, *wl;
    cudaGetSymbolAddress((void**)&xh, g_xh);
    cudaGetSymbolAddress((void**)&xl, g_xl);
    cudaGetSymbolAddress((void**)&wh, g_wh);
    cudaGetSymbolAddress((void**)&wl, g_wl);

    const int nx4 = BATCH * LSEQ * DDIM / 4;
    const int nw4 = DDIM * DDIM / 4;

    split_kernel<<<(nx4 + 255) / 256, 256>>>(x, xh, xl, nx4);
    split_kernel<<<(nw4 + 255) / 256, 256>>>(W, wh, wl, nw4);
    transpose_split_kernel<<<dim3(DDIM / 32, LSEQ / 32, BATCH), 256>>>(x);

    proj_gemm  <<<dim3(DDIM / 128, BATCH * LSEQ / 128), 256, SMEM_BYTES>>>(bias);
    scores_gemm<<<dim3(LSEQ / 128, LSEQ / 128, BATCH),  256, SMEM_BYTES>>>(x_mask);
    softmax_kernel<<<BATCH * LSEQ, 256>>>();
    av_gemm    <<<dim3(DDIM / 128, LSEQ / 128, BATCH),  256, SMEM_BYTES>>>(out);
}

// round 4
// speedup vs baseline: 2.3207x; 1.1321x over previous
#include <cuda_runtime.h>
#include <cuda_bf16.h>
#include <stdint.h>
#include <math.h>

#define BATCH 8
#define LSEQ  2048
#define DDIM  1024

typedef __nv_bfloat16 bf16;

// ---------------------------------------------------------------------------
// Scratch (device globals: no allocation allowed)
// ---------------------------------------------------------------------------
__device__ float g_scores[(size_t)BATCH * LSEQ * LSEQ];            // 134 MB
__device__ bf16  g_xh [(size_t)BATCH * LSEQ * DDIM];
__device__ bf16  g_xl [(size_t)BATCH * LSEQ * DDIM];
__device__ bf16  g_xth[(size_t)BATCH * DDIM * LSEQ];
__device__ bf16  g_xtl[(size_t)BATCH * DDIM * LSEQ];
__device__ bf16  g_wh [(size_t)DDIM * DDIM];
__device__ bf16  g_wl [(size_t)DDIM * DDIM];
__device__ bf16  g_ph [(size_t)BATCH * LSEQ * DDIM];
__device__ bf16  g_pl [(size_t)BATCH * LSEQ * DDIM];
__device__ bf16  g_ah [(size_t)BATCH * LSEQ * LSEQ];
__device__ bf16  g_al [(size_t)BATCH * LSEQ * LSEQ];

// ---------------------------------------------------------------------------
// PTX helpers (base sm_103 target — NO tcgen05)
// ---------------------------------------------------------------------------
__device__ __forceinline__ uint32_t smem_u32(const void* p) {
    uint32_t a;
    asm("{ .reg .u64 t; cvta.to.shared.u64 t, %1; cvt.u32.u64 %0, t; }" : "=r"(a) : "l"(p));
    return a;
}

__device__ __forceinline__ void cpa16(uint32_t d, const void* s) {
    asm volatile("cp.async.cg.shared.global [%0], [%1], 16;" :: "r"(d), "l"(s) : "memory");
}

#define CP_COMMIT() asm volatile("cp.async.commit_group;" ::: "memory")
#define CP_WAIT2()  asm volatile("cp.async.wait_group 2;" ::: "memory")

#define LDSM4(r, addr) \
    asm volatile("ldmatrix.sync.aligned.m8n8.x4.shared.b16 {%0,%1,%2,%3}, [%4];" \
        : "=r"((r)[0]), "=r"((r)[1]), "=r"((r)[2]), "=r"((r)[3]) : "r"(addr))

#define MMA(d, a, b0, b1) \
    asm volatile("mma.sync.aligned.m16n8k16.row.col.f32.bf16.bf16.f32 " \
        "{%0,%1,%2,%3}, {%4,%5,%6,%7}, {%8,%9}, {%0,%1,%2,%3};" \
        : "+f"((d)[0]), "+f"((d)[1]), "+f"((d)[2]), "+f"((d)[3]) \
        : "r"((a)[0]), "r"((a)[1]), "r"((a)[2]), "r"((a)[3]), "r"(b0), "r"(b1))

// ---------------------------------------------------------------------------
// GEMM core: C(128x128 fp32) = sum_k (Ah+Al)(Bh+Bl)^T via 3-pass bf16 HMMA.
// BK=32. Stage (32KB): A at +0, B at +16384; row = 128B [hi k0..31 | lo k0..31],
// XOR swizzle. 4 stages. 512 threads, 16 warps (4x4), warp tile 32x32.
// ---------------------------------------------------------------------------
#define NTH 512
#define NSTAGE 4
#define STG    32768
#define SMEM_BYTES (NSTAGE * STG)

__device__ __forceinline__ void issue_stage(uint32_t sb, int s, int tid,
    const bf16* __restrict__ Ah, const bf16* __restrict__ Al, size_t lda,
    const bf16* __restrict__ Bh, const bf16* __restrict__ Bl, size_t ldb, int kc)
{
    const uint32_t base = sb + (uint32_t)(s & 3) * STG;
    #pragma unroll
    for (int j = 0; j < 2; j++) {
        const int q   = tid + j * NTH;       // 0..1023
        const int row = q >> 3;
        const int c   = q & 7;               // chunk: 0-3 hi, 4-7 lo
        const uint32_t off = (uint32_t)(row * 128) + ((uint32_t)(c ^ (row & 7)) << 4);
        const bf16* sa = (c < 4) ? Ah + (size_t)row * lda + kc + c * 8
                                 : Al + (size_t)row * lda + kc + (c - 4) * 8;
        const bf16* sbp = (c < 4) ? Bh + (size_t)row * ldb + kc + c * 8
                                  : Bl + (size_t)row * ldb + kc + (c - 4) * 8;
        cpa16(base + off, sa);
        cpa16(base + 16384 + off, sbp);
    }
    CP_COMMIT();
}

__device__ __forceinline__ void compute_stage(uint32_t base, int m0, int n0, int lane,
                                              float acc[2][4][4])
{
    const int rA = lane & 15, cA = lane >> 4;
    const int rB = (lane & 7) + ((lane >> 4) << 3), cB = (lane >> 3) & 1;

    #pragma unroll
    for (int kk = 0; kk < 2; kk++) {
        const int cb = kk * 2;               // hi chunks cb, cb+1 ; lo at +4
        uint32_t aH[2][4], aL[2][4], bH[2][4], bL[2][4];

        #pragma unroll
        for (int mt = 0; mt < 2; mt++) {
            const uint32_t rowb = base + (uint32_t)((m0 + mt * 16 + rA) * 128);
            LDSM4(aH[mt], rowb + ((uint32_t)((cb + cA)     ^ (rA & 7)) << 4));
            LDSM4(aL[mt], rowb + ((uint32_t)((cb + 4 + cA) ^ (rA & 7)) << 4));
        }
        #pragma unroll
        for (int nt2 = 0; nt2 < 2; nt2++) {
            const uint32_t rowb = base + 16384 + (uint32_t)((n0 + nt2 * 16 + rB) * 128);
            LDSM4(bH[nt2], rowb + ((uint32_t)((cb + cB)     ^ (rB & 7)) << 4));
            LDSM4(bL[nt2], rowb + ((uint32_t)((cb + 4 + cB) ^ (rB & 7)) << 4));
        }
        // pass-major: 8 independent accumulators between reuses
        #pragma unroll
        for (int mt = 0; mt < 2; mt++)
            #pragma unroll
            for (int nt = 0; nt < 4; nt++) {
                const int g = nt >> 1, o = (nt & 1) * 2;
                MMA(acc[mt][nt], aH[mt], bH[g][o], bH[g][o + 1]);
            }
        #pragma unroll
        for (int mt = 0; mt < 2; mt++)
            #pragma unroll
            for (int nt = 0; nt < 4; nt++) {
                const int g = nt >> 1, o = (nt & 1) * 2;
                MMA(acc[mt][nt], aH[mt], bL[g][o], bL[g][o + 1]);
            }
        #pragma unroll
        for (int mt = 0; mt < 2; mt++)
            #pragma unroll
            for (int nt = 0; nt < 4; nt++) {
                const int g = nt >> 1, o = (nt & 1) * 2;
                MMA(acc[mt][nt], aL[mt], bH[g][o], bH[g][o + 1]);
            }
    }
}

__device__ __forceinline__ void run_gemm(uint32_t sb, int tid,
    const bf16* __restrict__ Ah, const bf16* __restrict__ Al, size_t lda,
    const bf16* __restrict__ Bh, const bf16* __restrict__ Bl, size_t ldb, int nk,
    float acc[2][4][4])
{
    #pragma unroll
    for (int mt = 0; mt < 2; mt++)
        #pragma unroll
        for (int nt = 0; nt < 4; nt++)
            #pragma unroll
            for (int i = 0; i < 4; i++) acc[mt][nt][i] = 0.f;

    issue_stage(sb, 0, tid, Ah, Al, lda, Bh, Bl, ldb, 0);
    issue_stage(sb, 1, tid, Ah, Al, lda, Bh, Bl, ldb, 32);
    issue_stage(sb, 2, tid, Ah, Al, lda, Bh, Bl, ldb, 64);

    const int wid = tid >> 5, lane = tid & 31;
    const int m0 = (wid & 3) * 32, n0 = (wid >> 2) * 32;

    for (int kt = 0; kt < nk; kt++) {
        CP_WAIT2();
        __syncthreads();
        if (kt + NSTAGE - 1 < nk)
            issue_stage(sb, kt + 3, tid, Ah, Al, lda, Bh, Bl, ldb, (kt + 3) * 32);
        else
            CP_COMMIT();
        compute_stage(sb + (uint32_t)(kt & 3) * STG, m0, n0, lane, acc);
    }
}

__device__ __forceinline__ uint32_t packbf(float a, float b) {
    __nv_bfloat162 t = __floats2bfloat162_rn(a, b);
    return *reinterpret_cast<uint32_t*>(&t);
}

// ---------------------------------------------------------------------------
// GEMM 1: proj = relu(x @ W^T + b) -> split bf16
// ---------------------------------------------------------------------------
__global__ __launch_bounds__(NTH, 1) void proj_gemm(const float* __restrict__ bias) {
    extern __shared__ char smem[];
    const uint32_t sb = smem_u32(smem);
    const int tid = threadIdx.x;
    const int mblk = blockIdx.y * 128, nblk = blockIdx.x * 128;

    float acc[2][4][4];
    run_gemm(sb, tid,
             g_xh + (size_t)mblk * DDIM, g_xl + (size_t)mblk * DDIM, DDIM,
             g_wh + (size_t)nblk * DDIM, g_wl + (size_t)nblk * DDIM, DDIM,
             DDIM / 32, acc);

    const int wid = tid >> 5, lane = tid & 31;
    const int m0 = (wid & 3) * 32, n0 = (wid >> 2) * 32;
    const int quad = lane >> 2, tq = lane & 3;

    #pragma unroll
    for (int mt = 0; mt < 2; mt++)
        #pragma unroll
        for (int nt = 0; nt < 4; nt++) {
            const int col = nblk + n0 + nt * 8 + tq * 2;
            const float b0 = bias[col], b1 = bias[col + 1];
            #pragma unroll
            for (int h = 0; h < 2; h++) {
                const int row = mblk + m0 + mt * 16 + quad + h * 8;
                float v0 = fmaxf(acc[mt][nt][h * 2 + 0] + b0, 0.f);
                float v1 = fmaxf(acc[mt][nt][h * 2 + 1] + b1, 0.f);
                bf16 h0 = __float2bfloat16(v0), h1 = __float2bfloat16(v1);
                float l0 = v0 - __bfloat162float(h0), l1 = v1 - __bfloat162float(h1);
                *reinterpret_cast<uint32_t*>(g_ph + (size_t)row * DDIM + col) =
                    packbf(__bfloat162float(h0), __bfloat162float(h1));
                *reinterpret_cast<uint32_t*>(g_pl + (size_t)row * DDIM + col) =
                    packbf(l0, l1);
            }
        }
}

// ---------------------------------------------------------------------------
// GEMM 2 (symmetric): for tile pairs ti<=tj compute P_ti @ P_tj^T once,
// write tile + mirrored tile via smem transpose. diag->0, masked key -> -inf.
// ---------------------------------------------------------------------------
__global__ __launch_bounds__(NTH, 1) void scores_gemm(const int* __restrict__ x_mask) {
    extern __shared__ char smem[];
    const uint32_t sb = smem_u32(smem);
    const int tid = threadIdx.x;
    const int b = blockIdx.y;
    int p = blockIdx.x;
    int ti = 0;
    while (p >= 16 - ti) { p -= 16 - ti; ti++; }
    const int tj = ti + p;
    const size_t pb = (size_t)b * LSEQ * DDIM;

    float acc[2][4][4];
    run_gemm(sb, tid,
             g_ph + pb + (size_t)ti * 128 * DDIM, g_pl + pb + (size_t)ti * 128 * DDIM, DDIM,
             g_ph + pb + (size_t)tj * 128 * DDIM, g_pl + pb + (size_t)tj * 128 * DDIM, DDIM,
             DDIM / 32, acc);

    // ---- stage tile into smem (reuse pipeline smem) ----
    __syncthreads();
    float (*sS)[129] = reinterpret_cast<float(*)[129]>(smem);
    int* smi = reinterpret_cast<int*>(smem + 128 * 129 * 4);        // 66048
    int* smj = smi + 128;

    const int wid = tid >> 5, lane = tid & 31;
    const int m0 = (wid & 3) * 32, n0 = (wid >> 2) * 32;
    const int quad = lane >> 2, tq = lane & 3;
    const int* mk = x_mask + (size_t)b * LSEQ;

    #pragma unroll
    for (int mt = 0; mt < 2; mt++)
        #pragma unroll
        for (int nt = 0; nt < 4; nt++) {
            const int c = n0 + nt * 8 + tq * 2;
            #pragma unroll
            for (int h = 0; h < 2; h++) {
                const int r = m0 + mt * 16 + quad + h * 8;
                sS[r][c]     = acc[mt][nt][h * 2 + 0];
                sS[r][c + 1] = acc[mt][nt][h * 2 + 1];
            }
        }
    if (tid < 128) { smi[tid] = mk[ti * 128 + tid]; smj[tid] = mk[tj * 128 + tid]; }
    __syncthreads();

    float* S = g_scores + (size_t)b * LSEQ * LSEQ;
    const float NEGINF = -INFINITY;
    const int r  = tid & 127;
    const int c0 = (tid >> 7) * 32;

    // normal tile: row gi = ti*128+r, cols tj*128 + c
    {
        float* Srow = S + (size_t)(ti * 128 + r) * LSEQ + tj * 128;
        #pragma unroll
        for (int cc = 0; cc < 32; cc += 4) {
            const int c = c0 + cc;
            float4 v;
            float x0 = sS[r][c],     x1 = sS[r][c + 1];
            float x2 = sS[r][c + 2], x3 = sS[r][c + 3];
            if (ti == tj) {
                if (r == c)     x0 = 0.f;
                if (r == c + 1) x1 = 0.f;
                if (r == c + 2) x2 = 0.f;
                if (r == c + 3) x3 = 0.f;
            }
            v.x = smj[c]     ? NEGINF : x0;
            v.y = smj[c + 1] ? NEGINF : x1;
            v.z = smj[c + 2] ? NEGINF : x2;
            v.w = smj[c + 3] ? NEGINF : x3;
            *reinterpret_cast<float4*>(Srow + c) = v;
        }
    }
    // mirror tile (ti != tj): row gj = tj*128+r, cols ti*128 + c, value sS[c][r]
    if (ti != tj) {
        float* Mrow = S + (size_t)(tj * 128 + r) * LSEQ + ti * 128;
        #pragma unroll
        for (int cc = 0; cc < 32; cc += 4) {
            const int c = c0 + cc;
            float4 v;
            v.x = smi[c]     ? NEGINF : sS[c][r];
            v.y = smi[c + 1] ? NEGINF : sS[c + 1][r];
            v.z = smi[c + 2] ? NEGINF : sS[c + 2][r];
            v.w = smi[c + 3] ? NEGINF : sS[c + 3][r];
            *reinterpret_cast<float4*>(Mrow + c) = v;
        }
    }
}

// ---------------------------------------------------------------------------
// GEMM 3: out = alpha @ x   (A = alpha split, B = x^T split)
// ---------------------------------------------------------------------------
__global__ __launch_bounds__(NTH, 1) void av_gemm(float* __restrict__ out) {
    extern __shared__ char smem[];
    const uint32_t sb = smem_u32(smem);
    const int tid = threadIdx.x;
    const int b = blockIdx.z;
    const int mblk = blockIdx.y * 128, nblk = blockIdx.x * 128;

    float acc[2][4][4];
    run_gemm(sb, tid,
             g_ah + ((size_t)b * LSEQ + mblk) * LSEQ, g_al + ((size_t)b * LSEQ + mblk) * LSEQ, LSEQ,
             g_xth + ((size_t)b * DDIM + nblk) * LSEQ, g_xtl + ((size_t)b * DDIM + nblk) * LSEQ, LSEQ,
             LSEQ / 32, acc);

    const int wid = tid >> 5, lane = tid & 31;
    const int m0 = (wid & 3) * 32, n0 = (wid >> 2) * 32;
    const int quad = lane >> 2, tq = lane & 3;

    #pragma unroll
    for (int mt = 0; mt < 2; mt++)
        #pragma unroll
        for (int nt = 0; nt < 4; nt++) {
            const int col = nblk + n0 + nt * 8 + tq * 2;
            #pragma unroll
            for (int h = 0; h < 2; h++) {
                const int row = mblk + m0 + mt * 16 + quad + h * 8;
                float2 o;
                o.x = acc[mt][nt][h * 2 + 0];
                o.y = acc[mt][nt][h * 2 + 1];
                *reinterpret_cast<float2*>(out + ((size_t)b * LSEQ + row) * DDIM + col) = o;
            }
        }
}

// ---------------------------------------------------------------------------
// Softmax over keys (fp32 scores in, split-bf16 alpha out)
// ---------------------------------------------------------------------------
__global__ __launch_bounds__(256) void softmax_kernel() {
    const size_t row = blockIdx.x;
    const float* p = g_scores + row * LSEQ;
    const int t = threadIdx.x;

    float4 v0 = reinterpret_cast<const float4*>(p)[t * 2];
    float4 v1 = reinterpret_cast<const float4*>(p)[t * 2 + 1];

    float m = fmaxf(fmaxf(fmaxf(v0.x, v0.y), fmaxf(v0.z, v0.w)),
                    fmaxf(fmaxf(v1.x, v1.y), fmaxf(v1.z, v1.w)));

    __shared__ float red[8];
    #pragma unroll
    for (int off = 16; off > 0; off >>= 1)
        m = fmaxf(m, __shfl_xor_sync(0xffffffffu, m, off));
    if ((t & 31) == 0) red[t >> 5] = m;
    __syncthreads();
    if (t == 0) {
        float mm = red[0];
        #pragma unroll
        for (int w = 1; w < 8; w++) mm = fmaxf(mm, red[w]);
        red[0] = mm;
    }
    __syncthreads();
    m = red[0];
    __syncthreads();

    float e[8];
    e[0] = expf(v0.x - m); e[1] = expf(v0.y - m); e[2] = expf(v0.z - m); e[3] = expf(v0.w - m);
    e[4] = expf(v1.x - m); e[5] = expf(v1.y - m); e[6] = expf(v1.z - m); e[7] = expf(v1.w - m);
    float s = e[0] + e[1] + e[2] + e[3] + e[4] + e[5] + e[6] + e[7];
    #pragma unroll
    for (int off = 16; off > 0; off >>= 1)
        s += __shfl_xor_sync(0xffffffffu, s, off);
    if ((t & 31) == 0) red[t >> 5] = s;
    __syncthreads();
    if (t == 0) {
        float ss = 0.f;
        #pragma unroll
        for (int w = 0; w < 8; w++) ss += red[w];
        red[0] = ss;
    }
    __syncthreads();
    const float inv = 1.0f / red[0];

    uint32_t hh[4], ll[4];
    #pragma unroll
    for (int i = 0; i < 4; i++) {
        float a0 = e[2 * i] * inv, a1 = e[2 * i + 1] * inv;
        bf16 h0 = __float2bfloat16(a0), h1 = __float2bfloat16(a1);
        hh[i] = packbf(__bfloat162float(h0), __bfloat162float(h1));
        ll[i] = packbf(a0 - __bfloat162float(h0), a1 - __bfloat162float(h1));
    }
    *reinterpret_cast<uint4*>(g_ah + row * LSEQ + t * 8) = *reinterpret_cast<uint4*>(hh);
    *reinterpret_cast<uint4*>(g_al + row * LSEQ + t * 8) = *reinterpret_cast<uint4*>(ll);
}

// ---------------------------------------------------------------------------
// fp32 -> split-bf16 conversions
// ---------------------------------------------------------------------------
__global__ __launch_bounds__(256) void split_kernel(const float* __restrict__ s,
                                                    bf16* __restrict__ hi,
                                                    bf16* __restrict__ lo, int n4) {
    const int i = blockIdx.x * 256 + threadIdx.x;
    if (i >= n4) return;
    float4 v = reinterpret_cast<const float4*>(s)[i];
    bf16 h0 = __float2bfloat16(v.x), h1 = __float2bfloat16(v.y);
    bf16 h2 = __float2bfloat16(v.z), h3 = __float2bfloat16(v.w);
    uint2 uh, ul;
    uh.x = packbf(__bfloat162float(h0), __bfloat162float(h1));
    uh.y = packbf(__bfloat162float(h2), __bfloat162float(h3));
    ul.x = packbf(v.x - __bfloat162float(h0), v.y - __bfloat162float(h1));
    ul.y = packbf(v.z - __bfloat162float(h2), v.w - __bfloat162float(h3));
    reinterpret_cast<uint2*>(hi)[i] = uh;
    reinterpret_cast<uint2*>(lo)[i] = ul;
}

// x[b][l][d] -> xt[b][d][l], split bf16
__global__ __launch_bounds__(256) void transpose_split_kernel(const float* __restrict__ x) {
    __shared__ float t[32][33];
    const int b = blockIdx.z, d0 = blockIdx.x * 32, l0 = blockIdx.y * 32;
    const int tx = threadIdx.x & 31, ty = threadIdx.x >> 5;   // 32 x 8
    const float* xb = x + (size_t)b * LSEQ * DDIM;
    #pragma unroll
    for (int j = 0; j < 4; j++)
        t[ty + j * 8][tx] = xb[(size_t)(l0 + ty + j * 8) * DDIM + d0 + tx];
    __syncthreads();
    bf16* oh = g_xth + (size_t)b * DDIM * LSEQ;
    bf16* ol = g_xtl + (size_t)b * DDIM * LSEQ;
    #pragma unroll
    for (int j = 0; j < 4; j++) {
        float v = t[tx][ty + j * 8];
        bf16 h = __float2bfloat16(v);
        float lo = v - __bfloat162float(h);
        const size_t o = (size_t)(d0 + ty + j * 8) * LSEQ + l0 + tx;
        oh[o] = h;
        ol[o] = __float2bfloat16(lo);
    }
}

// ---------------------------------------------------------------------------
extern "C" void kernel_launch(void* const* d_in, const int* in_sizes, int n_in,
                              void* d_out, int out_size) {
    const float* x      = (const float*)d_in[0];   // [8, 2048, 1024]
    const int*   x_mask = (const int*)d_in[1];     // [8, 2048]
    const float* W      = (const float*)d_in[2];   // [1024, 1024]
    const float* bias   = (const float*)d_in[3];   // [1024]
    float* out = (float*)d_out;                    // [8, 2048, 1024]

    cudaFuncSetAttribute(proj_gemm,   cudaFuncAttributeMaxDynamicSharedMemorySize, SMEM_BYTES);
    cudaFuncSetAttribute(scores_gemm, cudaFuncAttributeMaxDynamicSharedMemorySize, SMEM_BYTES);
    cudaFuncSetAttribute(av_gemm,     cudaFuncAttributeMaxDynamicSharedMemorySize, SMEM_BYTES);

    bf16 *xh, *xl, *wh, *wl;
    cudaGetSymbolAddress((void**)&xh, g_xh);
    cudaGetSymbolAddress((void**)&xl, g_xl);
    cudaGetSymbolAddress((void**)&wh, g_wh);
    cudaGetSymbolAddress((void**)&wl, g_wl);

    const int nx4 = BATCH * LSEQ * DDIM / 4;
    const int nw4 = DDIM * DDIM / 4;

    split_kernel<<<(nx4 + 255) / 256, 256>>>(x, xh, xl, nx4);
    split_kernel<<<(nw4 + 255) / 256, 256>>>(W, wh, wl, nw4);
    transpose_split_kernel<<<dim3(DDIM / 32, LSEQ / 32, BATCH), 256>>>(x);

    proj_gemm  <<<dim3(DDIM / 128, BATCH * LSEQ / 128), NTH, SMEM_BYTES>>>(bias);
    scores_gemm<<<dim3(136, BATCH), NTH, SMEM_BYTES>>>(x_mask);
    softmax_kernel<<<BATCH * LSEQ, 256>>>();
    av_gemm    <<<dim3(DDIM / 128, LSEQ / 128, BATCH), NTH, SMEM_BYTES>>>(out);
}

// round 5
// speedup vs baseline: 2.9933x; 1.2898x over previous
#include <cuda_runtime.h>
#include <cuda_bf16.h>
#include <stdint.h>
#include <math.h>

#define BATCH 8
#define LSEQ  2048
#define DDIM  1024

typedef __nv_bfloat16 bf16;

// ---------------------------------------------------------------------------
// Scratch (device globals: no allocation allowed)
// ---------------------------------------------------------------------------
__device__ float g_scores[(size_t)BATCH * LSEQ * LSEQ];            // 134 MB
__device__ bf16  g_xh [(size_t)BATCH * LSEQ * DDIM];
__device__ bf16  g_xl [(size_t)BATCH * LSEQ * DDIM];
__device__ bf16  g_xth[(size_t)BATCH * DDIM * LSEQ];
__device__ bf16  g_xtl[(size_t)BATCH * DDIM * LSEQ];
__device__ bf16  g_wh [(size_t)DDIM * DDIM];
__device__ bf16  g_wl [(size_t)DDIM * DDIM];
__device__ bf16  g_ph [(size_t)BATCH * LSEQ * DDIM];
__device__ bf16  g_pl [(size_t)BATCH * LSEQ * DDIM];
__device__ bf16  g_ah [(size_t)BATCH * LSEQ * LSEQ];
__device__ bf16  g_al [(size_t)BATCH * LSEQ * LSEQ];

// ---------------------------------------------------------------------------
// PTX helpers (base sm_103 target — NO tcgen05)
// ---------------------------------------------------------------------------
__device__ __forceinline__ uint32_t smem_u32(const void* p) {
    uint32_t a;
    asm("{ .reg .u64 t; cvta.to.shared.u64 t, %1; cvt.u32.u64 %0, t; }" : "=r"(a) : "l"(p));
    return a;
}

__device__ __forceinline__ void cpa16(uint32_t d, const void* s) {
    asm volatile("cp.async.cg.shared.global [%0], [%1], 16;" :: "r"(d), "l"(s) : "memory");
}

#define CP_COMMIT() asm volatile("cp.async.commit_group;" ::: "memory")
#define CP_WAIT1()  asm volatile("cp.async.wait_group 1;" ::: "memory")

#define LDSM4(r, addr) \
    asm volatile("ldmatrix.sync.aligned.m8n8.x4.shared.b16 {%0,%1,%2,%3}, [%4];" \
        : "=r"((r)[0]), "=r"((r)[1]), "=r"((r)[2]), "=r"((r)[3]) : "r"(addr))

#define MMA(d, a, b0, b1) \
    asm volatile("mma.sync.aligned.m16n8k16.row.col.f32.bf16.bf16.f32 " \
        "{%0,%1,%2,%3}, {%4,%5,%6,%7}, {%8,%9}, {%0,%1,%2,%3};" \
        : "+f"((d)[0]), "+f"((d)[1]), "+f"((d)[2]), "+f"((d)[3]) \
        : "r"((a)[0]), "r"((a)[1]), "r"((a)[2]), "r"((a)[3]), "r"(b0), "r"(b1))

// ---------------------------------------------------------------------------
// GEMM core: C(128x128 fp32) = sum_k (Ah+Al)(Bh+Bl)^T via 3-pass bf16 HMMA.
// BK=32. Stage (32KB): A at +0, B at +16384; row = 128B [hi k0..31 | lo k0..31],
// XOR swizzle. 4 stages, cp.async. 512 threads, 16 warps (4x4), warp 32x32.
// Fragment loads are register-double-buffered to hide LDSM latency.
// ---------------------------------------------------------------------------
#define NTH 512
#define NSTAGE 4
#define STG    32768
#define SMEM_BYTES (NSTAGE * STG)

struct Frag {
    uint32_t aH[2][4], aL[2][4], bH[2][4], bL[2][4];
};

__device__ __forceinline__ void issue_stage(uint32_t sb, int s, int tid,
    const bf16* __restrict__ Ah, const bf16* __restrict__ Al, size_t lda,
    const bf16* __restrict__ Bh, const bf16* __restrict__ Bl, size_t ldb, int kc)
{
    const uint32_t base = sb + (uint32_t)(s & 3) * STG;
    #pragma unroll
    for (int j = 0; j < 2; j++) {
        const int q   = tid + j * NTH;       // 0..1023
        const int row = q >> 3;
        const int c   = q & 7;               // chunk: 0-3 hi, 4-7 lo
        const uint32_t off = (uint32_t)(row * 128) + ((uint32_t)(c ^ (row & 7)) << 4);
        const bf16* sa = (c < 4) ? Ah + (size_t)row * lda + kc + c * 8
                                 : Al + (size_t)row * lda + kc + (c - 4) * 8;
        const bf16* sbp = (c < 4) ? Bh + (size_t)row * ldb + kc + c * 8
                                  : Bl + (size_t)row * ldb + kc + (c - 4) * 8;
        cpa16(base + off, sa);
        cpa16(base + 16384 + off, sbp);
    }
    CP_COMMIT();
}

__device__ __forceinline__ void load_frags(uint32_t base, int kk, int m0, int n0,
                                           int lane, Frag& f)
{
    const int rA = lane & 15, cA = lane >> 4;
    const int rB = (lane & 7) + ((lane >> 4) << 3), cB = (lane >> 3) & 1;
    const int cb = kk * 2;
    #pragma unroll
    for (int mt = 0; mt < 2; mt++) {
        const uint32_t rowb = base + (uint32_t)((m0 + mt * 16 + rA) * 128);
        LDSM4(f.aH[mt], rowb + ((uint32_t)((cb + cA)     ^ (rA & 7)) << 4));
        LDSM4(f.aL[mt], rowb + ((uint32_t)((cb + 4 + cA) ^ (rA & 7)) << 4));
    }
    #pragma unroll
    for (int nt2 = 0; nt2 < 2; nt2++) {
        const uint32_t rowb = base + 16384 + (uint32_t)((n0 + nt2 * 16 + rB) * 128);
        LDSM4(f.bH[nt2], rowb + ((uint32_t)((cb + cB)     ^ (rB & 7)) << 4));
        LDSM4(f.bL[nt2], rowb + ((uint32_t)((cb + 4 + cB) ^ (rB & 7)) << 4));
    }
}

__device__ __forceinline__ void do_mmas(const Frag& f, float acc[2][4][4]) {
    // pass-major: 8 independent accumulators between reuses
    #pragma unroll
    for (int mt = 0; mt < 2; mt++)
        #pragma unroll
        for (int nt = 0; nt < 4; nt++) {
            const int g = nt >> 1, o = (nt & 1) * 2;
            MMA(acc[mt][nt], f.aH[mt], f.bH[g][o], f.bH[g][o + 1]);
        }
    #pragma unroll
    for (int mt = 0; mt < 2; mt++)
        #pragma unroll
        for (int nt = 0; nt < 4; nt++) {
            const int g = nt >> 1, o = (nt & 1) * 2;
            MMA(acc[mt][nt], f.aH[mt], f.bL[g][o], f.bL[g][o + 1]);
        }
    #pragma unroll
    for (int mt = 0; mt < 2; mt++)
        #pragma unroll
        for (int nt = 0; nt < 4; nt++) {
            const int g = nt >> 1, o = (nt & 1) * 2;
            MMA(acc[mt][nt], f.aL[mt], f.bH[g][o], f.bH[g][o + 1]);
        }
}

__device__ __forceinline__ void run_gemm(uint32_t sb, int tid,
    const bf16* __restrict__ Ah, const bf16* __restrict__ Al, size_t lda,
    const bf16* __restrict__ Bh, const bf16* __restrict__ Bl, size_t ldb, int nk,
    float acc[2][4][4])
{
    #pragma unroll
    for (int mt = 0; mt < 2; mt++)
        #pragma unroll
        for (int nt = 0; nt < 4; nt++)
            #pragma unroll
            for (int i = 0; i < 4; i++) acc[mt][nt][i] = 0.f;

    issue_stage(sb, 0, tid, Ah, Al, lda, Bh, Bl, ldb, 0);
    issue_stage(sb, 1, tid, Ah, Al, lda, Bh, Bl, ldb, 32);
    issue_stage(sb, 2, tid, Ah, Al, lda, Bh, Bl, ldb, 64);

    const int wid = tid >> 5, lane = tid & 31;
    const int m0 = (wid & 3) * 32, n0 = (wid >> 2) * 32;

    CP_WAIT1();                 // stages 0 and 1 resident
    __syncthreads();

    Frag fa, fb;
    load_frags(sb, 0, m0, n0, lane, fa);   // stage 0, kk=0

    for (int kt = 0; kt < nk; kt++) {
        const uint32_t cur = sb + (uint32_t)(kt & 3) * STG;
        // refill stage kt+3 (overwrites buffer of kt-1; safe: sync at end of prev iter)
        if (kt + 3 < nk)
            issue_stage(sb, kt + 3, tid, Ah, Al, lda, Bh, Bl, ldb, (kt + 3) * 32);
        else
            CP_COMMIT();

        load_frags(cur, 1, m0, n0, lane, fb);     // prefetch kk=1 of current stage
        do_mmas(fa, acc);

        const int pkt = (kt + 1 < nk) ? kt + 1 : kt;   // next stage (resident via WAIT1)
        load_frags(sb + (uint32_t)(pkt & 3) * STG, 0, m0, n0, lane, fa);
        do_mmas(fb, acc);

        CP_WAIT1();             // ensure stages kt+1, kt+2 resident for next iter
        __syncthreads();
    }
}

__device__ __forceinline__ uint32_t packbf(float a, float b) {
    __nv_bfloat162 t = __floats2bfloat162_rn(a, b);
    return *reinterpret_cast<uint32_t*>(&t);
}

// ---------------------------------------------------------------------------
// GEMM 1: proj = relu(x @ W^T + b) -> split bf16
// ---------------------------------------------------------------------------
__global__ __launch_bounds__(NTH, 1) void proj_gemm(const float* __restrict__ bias) {
    extern __shared__ char smem[];
    const uint32_t sb = smem_u32(smem);
    const int tid = threadIdx.x;
    const int mblk = blockIdx.y * 128, nblk = blockIdx.x * 128;

    float acc[2][4][4];
    run_gemm(sb, tid,
             g_xh + (size_t)mblk * DDIM, g_xl + (size_t)mblk * DDIM, DDIM,
             g_wh + (size_t)nblk * DDIM, g_wl + (size_t)nblk * DDIM, DDIM,
             DDIM / 32, acc);

    const int wid = tid >> 5, lane = tid & 31;
    const int m0 = (wid & 3) * 32, n0 = (wid >> 2) * 32;
    const int quad = lane >> 2, tq = lane & 3;

    #pragma unroll
    for (int mt = 0; mt < 2; mt++)
        #pragma unroll
        for (int nt = 0; nt < 4; nt++) {
            const int col = nblk + n0 + nt * 8 + tq * 2;
            const float b0 = bias[col], b1 = bias[col + 1];
            #pragma unroll
            for (int h = 0; h < 2; h++) {
                const int row = mblk + m0 + mt * 16 + quad + h * 8;
                float v0 = fmaxf(acc[mt][nt][h * 2 + 0] + b0, 0.f);
                float v1 = fmaxf(acc[mt][nt][h * 2 + 1] + b1, 0.f);
                bf16 h0 = __float2bfloat16(v0), h1 = __float2bfloat16(v1);
                float l0 = v0 - __bfloat162float(h0), l1 = v1 - __bfloat162float(h1);
                *reinterpret_cast<uint32_t*>(g_ph + (size_t)row * DDIM + col) =
                    packbf(__bfloat162float(h0), __bfloat162float(h1));
                *reinterpret_cast<uint32_t*>(g_pl + (size_t)row * DDIM + col) =
                    packbf(l0, l1);
            }
        }
}

// ---------------------------------------------------------------------------
// GEMM 2 (symmetric): for tile pairs ti<=tj compute P_ti @ P_tj^T once,
// write tile + mirrored tile via smem transpose. diag->0, masked key -> -inf.
// ---------------------------------------------------------------------------
__global__ __launch_bounds__(NTH, 1) void scores_gemm(const int* __restrict__ x_mask) {
    extern __shared__ char smem[];
    const uint32_t sb = smem_u32(smem);
    const int tid = threadIdx.x;
    const int b = blockIdx.y;
    int p = blockIdx.x;
    int ti = 0;
    while (p >= 16 - ti) { p -= 16 - ti; ti++; }
    const int tj = ti + p;
    const size_t pb = (size_t)b * LSEQ * DDIM;

    float acc[2][4][4];
    run_gemm(sb, tid,
             g_ph + pb + (size_t)ti * 128 * DDIM, g_pl + pb + (size_t)ti * 128 * DDIM, DDIM,
             g_ph + pb + (size_t)tj * 128 * DDIM, g_pl + pb + (size_t)tj * 128 * DDIM, DDIM,
             DDIM / 32, acc);

    // ---- stage tile into smem (reuse pipeline smem) ----
    __syncthreads();
    float (*sS)[129] = reinterpret_cast<float(*)[129]>(smem);
    int* smi = reinterpret_cast<int*>(smem + 128 * 129 * 4);        // 66048
    int* smj = smi + 128;

    const int wid = tid >> 5, lane = tid & 31;
    const int m0 = (wid & 3) * 32, n0 = (wid >> 2) * 32;
    const int quad = lane >> 2, tq = lane & 3;
    const int* mk = x_mask + (size_t)b * LSEQ;

    #pragma unroll
    for (int mt = 0; mt < 2; mt++)
        #pragma unroll
        for (int nt = 0; nt < 4; nt++) {
            const int c = n0 + nt * 8 + tq * 2;
            #pragma unroll
            for (int h = 0; h < 2; h++) {
                const int r = m0 + mt * 16 + quad + h * 8;
                sS[r][c]     = acc[mt][nt][h * 2 + 0];
                sS[r][c + 1] = acc[mt][nt][h * 2 + 1];
            }
        }
    if (tid < 128) { smi[tid] = mk[ti * 128 + tid]; smj[tid] = mk[tj * 128 + tid]; }
    __syncthreads();

    float* S = g_scores + (size_t)b * LSEQ * LSEQ;
    const float NEGINF = -INFINITY;
    const int r  = tid & 127;
    const int c0 = (tid >> 7) * 32;

    // normal tile: row gi = ti*128+r, cols tj*128 + c
    {
        float* Srow = S + (size_t)(ti * 128 + r) * LSEQ + tj * 128;
        #pragma unroll
        for (int cc = 0; cc < 32; cc += 4) {
            const int c = c0 + cc;
            float4 v;
            float x0 = sS[r][c],     x1 = sS[r][c + 1];
            float x2 = sS[r][c + 2], x3 = sS[r][c + 3];
            if (ti == tj) {
                if (r == c)     x0 = 0.f;
                if (r == c + 1) x1 = 0.f;
                if (r == c + 2) x2 = 0.f;
                if (r == c + 3) x3 = 0.f;
            }
            v.x = smj[c]     ? NEGINF : x0;
            v.y = smj[c + 1] ? NEGINF : x1;
            v.z = smj[c + 2] ? NEGINF : x2;
            v.w = smj[c + 3] ? NEGINF : x3;
            *reinterpret_cast<float4*>(Srow + c) = v;
        }
    }
    // mirror tile (ti != tj): row gj = tj*128+r, cols ti*128 + c, value sS[c][r]
    if (ti != tj) {
        float* Mrow = S + (size_t)(tj * 128 + r) * LSEQ + ti * 128;
        #pragma unroll
        for (int cc = 0; cc < 32; cc += 4) {
            const int c = c0 + cc;
            float4 v;
            v.x = smi[c]     ? NEGINF : sS[c][r];
            v.y = smi[c + 1] ? NEGINF : sS[c + 1][r];
            v.z = smi[c + 2] ? NEGINF : sS[c + 2][r];
            v.w = smi[c + 3] ? NEGINF : sS[c + 3][r];
            *reinterpret_cast<float4*>(Mrow + c) = v;
        }
    }
}

// ---------------------------------------------------------------------------
// GEMM 3: out = alpha @ x   (A = alpha split, B = x^T split)
// ---------------------------------------------------------------------------
__global__ __launch_bounds__(NTH, 1) void av_gemm(float* __restrict__ out) {
    extern __shared__ char smem[];
    const uint32_t sb = smem_u32(smem);
    const int tid = threadIdx.x;
    const int b = blockIdx.z;
    const int mblk = blockIdx.y * 128, nblk = blockIdx.x * 128;

    float acc[2][4][4];
    run_gemm(sb, tid,
             g_ah + ((size_t)b * LSEQ + mblk) * LSEQ, g_al + ((size_t)b * LSEQ + mblk) * LSEQ, LSEQ,
             g_xth + ((size_t)b * DDIM + nblk) * LSEQ, g_xtl + ((size_t)b * DDIM + nblk) * LSEQ, LSEQ,
             LSEQ / 32, acc);

    const int wid = tid >> 5, lane = tid & 31;
    const int m0 = (wid & 3) * 32, n0 = (wid >> 2) * 32;
    const int quad = lane >> 2, tq = lane & 3;

    #pragma unroll
    for (int mt = 0; mt < 2; mt++)
        #pragma unroll
        for (int nt = 0; nt < 4; nt++) {
            const int col = nblk + n0 + nt * 8 + tq * 2;
            #pragma unroll
            for (int h = 0; h < 2; h++) {
                const int row = mblk + m0 + mt * 16 + quad + h * 8;
                float2 o;
                o.x = acc[mt][nt][h * 2 + 0];
                o.y = acc[mt][nt][h * 2 + 1];
                *reinterpret_cast<float2*>(out + ((size_t)b * LSEQ + row) * DDIM + col) = o;
            }
        }
}

// ---------------------------------------------------------------------------
// Softmax over keys (fp32 scores in, split-bf16 alpha out)
// ---------------------------------------------------------------------------
__global__ __launch_bounds__(256) void softmax_kernel() {
    const size_t row = blockIdx.x;
    const float* p = g_scores + row * LSEQ;
    const int t = threadIdx.x;

    float4 v0 = reinterpret_cast<const float4*>(p)[t * 2];
    float4 v1 = reinterpret_cast<const float4*>(p)[t * 2 + 1];

    float m = fmaxf(fmaxf(fmaxf(v0.x, v0.y), fmaxf(v0.z, v0.w)),
                    fmaxf(fmaxf(v1.x, v1.y), fmaxf(v1.z, v1.w)));

    __shared__ float red[8];
    #pragma unroll
    for (int off = 16; off > 0; off >>= 1)
        m = fmaxf(m, __shfl_xor_sync(0xffffffffu, m, off));
    if ((t & 31) == 0) red[t >> 5] = m;
    __syncthreads();
    if (t == 0) {
        float mm = red[0];
        #pragma unroll
        for (int w = 1; w < 8; w++) mm = fmaxf(mm, red[w]);
        red[0] = mm;
    }
    __syncthreads();
    m = red[0];
    __syncthreads();

    float e[8];
    e[0] = expf(v0.x - m); e[1] = expf(v0.y - m); e[2] = expf(v0.z - m); e[3] = expf(v0.w - m);
    e[4] = expf(v1.x - m); e[5] = expf(v1.y - m); e[6] = expf(v1.z - m); e[7] = expf(v1.w - m);
    float s = e[0] + e[1] + e[2] + e[3] + e[4] + e[5] + e[6] + e[7];
    #pragma unroll
    for (int off = 16; off > 0; off >>= 1)
        s += __shfl_xor_sync(0xffffffffu, s, off);
    if ((t & 31) == 0) red[t >> 5] = s;
    __syncthreads();
    if (t == 0) {
        float ss = 0.f;
        #pragma unroll
        for (int w = 0; w < 8; w++) ss += red[w];
        red[0] = ss;
    }
    __syncthreads();
    const float inv = 1.0f / red[0];

    uint32_t hh[4], ll[4];
    #pragma unroll
    for (int i = 0; i < 4; i++) {
        float a0 = e[2 * i] * inv, a1 = e[2 * i + 1] * inv;
        bf16 h0 = __float2bfloat16(a0), h1 = __float2bfloat16(a1);
        hh[i] = packbf(__bfloat162float(h0), __bfloat162float(h1));
        ll[i] = packbf(a0 - __bfloat162float(h0), a1 - __bfloat162float(h1));
    }
    *reinterpret_cast<uint4*>(g_ah + row * LSEQ + t * 8) = *reinterpret_cast<uint4*>(hh);
    *reinterpret_cast<uint4*>(g_al + row * LSEQ + t * 8) = *reinterpret_cast<uint4*>(ll);
}

// ---------------------------------------------------------------------------
// fp32 -> split-bf16 conversions
// ---------------------------------------------------------------------------
__global__ __launch_bounds__(256) void split_kernel(const float* __restrict__ s,
                                                    bf16* __restrict__ hi,
                                                    bf16* __restrict__ lo, int n4) {
    const int i = blockIdx.x * 256 + threadIdx.x;
    if (i >= n4) return;
    float4 v = reinterpret_cast<const float4*>(s)[i];
    bf16 h0 = __float2bfloat16(v.x), h1 = __float2bfloat16(v.y);
    bf16 h2 = __float2bfloat16(v.z), h3 = __float2bfloat16(v.w);
    uint2 uh, ul;
    uh.x = packbf(__bfloat162float(h0), __bfloat162float(h1));
    uh.y = packbf(__bfloat162float(h2), __bfloat162float(h3));
    ul.x = packbf(v.x - __bfloat162float(h0), v.y - __bfloat162float(h1));
    ul.y = packbf(v.z - __bfloat162float(h2), v.w - __bfloat162float(h3));
    reinterpret_cast<uint2*>(hi)[i] = uh;
    reinterpret_cast<uint2*>(lo)[i] = ul;
}

// x[b][l][d] -> xt[b][d][l], split bf16
__global__ __launch_bounds__(256) void transpose_split_kernel(const float* __restrict__ x) {
    __shared__ float t[32][33];
    const int b = blockIdx.z, d0 = blockIdx.x * 32, l0 = blockIdx.y * 32;
    const int tx = threadIdx.x & 31, ty = threadIdx.x >> 5;   // 32 x 8
    const float* xb = x + (size_t)b * LSEQ * DDIM;
    #pragma unroll
    for (int j = 0; j < 4; j++)
        t[ty + j * 8][tx] = xb[(size_t)(l0 + ty + j * 8) * DDIM + d0 + tx];
    __syncthreads();
    bf16* oh = g_xth + (size_t)b * DDIM * LSEQ;
    bf16* ol = g_xtl + (size_t)b * DDIM * LSEQ;
    #pragma unroll
    for (int j = 0; j < 4; j++) {
        float v = t[tx][ty + j * 8];
        bf16 h = __float2bfloat16(v);
        float lo = v - __bfloat162float(h);
        const size_t o = (size_t)(d0 + ty + j * 8) * LSEQ + l0 + tx;
        oh[o] = h;
        ol[o] = __float2bfloat16(lo);
    }
}

// ---------------------------------------------------------------------------
extern "C" void kernel_launch(void* const* d_in, const int* in_sizes, int n_in,
                              void* d_out, int out_size) {
    const float* x      = (const float*)d_in[0];   // [8, 2048, 1024]
    const int*   x_mask = (const int*)d_in[1];     // [8, 2048]
    const float* W      = (const float*)d_in[2];   // [1024, 1024]
    const float* bias   = (const float*)d_in[3];   // [1024]
    float* out = (float*)d_out;                    // [8, 2048, 1024]

    cudaFuncSetAttribute(proj_gemm,   cudaFuncAttributeMaxDynamicSharedMemorySize, SMEM_BYTES);
    cudaFuncSetAttribute(scores_gemm, cudaFuncAttributeMaxDynamicSharedMemorySize, SMEM_BYTES);
    cudaFuncSetAttribute(av_gemm,     cudaFuncAttributeMaxDynamicSharedMemorySize, SMEM_BYTES);

    bf16 *xh, *xl, *wh, *wl;
    cudaGetSymbolAddress((void**)&xh, g_xh);
    cudaGetSymbolAddress((void**)&xl, g_xl);
    cudaGetSymbolAddress((void**)&wh, g_wh);
    cudaGetSymbolAddress((void**)&wl, g_wl);

    const int nx4 = BATCH * LSEQ * DDIM / 4;
    const int nw4 = DDIM * DDIM / 4;

    split_kernel<<<(nx4 + 255) / 256, 256>>>(x, xh, xl, nx4);
    split_kernel<<<(nw4 + 255) / 256, 256>>>(W, wh, wl, nw4);
    transpose_split_kernel<<<dim3(DDIM / 32, LSEQ / 32, BATCH), 256>>>(x);

    proj_gemm  <<<dim3(DDIM / 128, (BATCH * LSEQ) / 128), NTH, SMEM_BYTES>>>(bias);
    scores_gemm<<<dim3(136, BATCH), NTH, SMEM_BYTES>>>(x_mask);
    softmax_kernel<<<BATCH * LSEQ, 256>>>();
    av_gemm    <<<dim3(DDIM / 128, LSEQ / 128, BATCH), NTH, SMEM_BYTES>>>(out);
}

// round 6
// speedup vs baseline: 3.0574x; 1.0214x over previous
#include <cuda_runtime.h>
#include <cuda_bf16.h>
#include <stdint.h>
#include <math.h>

#define BATCH 8
#define LSEQ  2048
#define DDIM  1024

typedef __nv_bfloat16 bf16;

// ---------------------------------------------------------------------------
// Scratch (device globals: no allocation allowed)
// ---------------------------------------------------------------------------
__device__ float g_scores[(size_t)BATCH * LSEQ * LSEQ];            // 134 MB
__device__ bf16  g_xh [(size_t)BATCH * LSEQ * DDIM];
__device__ bf16  g_xl [(size_t)BATCH * LSEQ * DDIM];
__device__ bf16  g_xth[(size_t)BATCH * DDIM * LSEQ];
__device__ bf16  g_xtl[(size_t)BATCH * DDIM * LSEQ];
__device__ bf16  g_wh [(size_t)DDIM * DDIM];
__device__ bf16  g_wl [(size_t)DDIM * DDIM];
__device__ bf16  g_ph [(size_t)BATCH * LSEQ * DDIM];
__device__ bf16  g_pl [(size_t)BATCH * LSEQ * DDIM];
__device__ bf16  g_ah [(size_t)BATCH * LSEQ * LSEQ];
__device__ bf16  g_al [(size_t)BATCH * LSEQ * LSEQ];

// ---------------------------------------------------------------------------
// PTX helpers (base sm_103 target — NO tcgen05)
// ---------------------------------------------------------------------------
__device__ __forceinline__ uint32_t smem_u32(const void* p) {
    uint32_t a;
    asm("{ .reg .u64 t; cvta.to.shared.u64 t, %1; cvt.u32.u64 %0, t; }" : "=r"(a) : "l"(p));
    return a;
}

__device__ __forceinline__ void cpa16(uint32_t d, const void* s) {
    asm volatile("cp.async.cg.shared.global [%0], [%1], 16;" :: "r"(d), "l"(s) : "memory");
}

#define CP_COMMIT() asm volatile("cp.async.commit_group;" ::: "memory")
#define CP_WAIT1()  asm volatile("cp.async.wait_group 1;" ::: "memory")

#define LDSM4(r, addr) \
    asm volatile("ldmatrix.sync.aligned.m8n8.x4.shared.b16 {%0,%1,%2,%3}, [%4];" \
        : "=r"((r)[0]), "=r"((r)[1]), "=r"((r)[2]), "=r"((r)[3]) : "r"(addr))

#define MMA(d, a, b0, b1) \
    asm volatile("mma.sync.aligned.m16n8k16.row.col.f32.bf16.bf16.f32 " \
        "{%0,%1,%2,%3}, {%4,%5,%6,%7}, {%8,%9}, {%0,%1,%2,%3};" \
        : "+f"((d)[0]), "+f"((d)[1]), "+f"((d)[2]), "+f"((d)[3]) \
        : "r"((a)[0]), "r"((a)[1]), "r"((a)[2]), "r"((a)[3]), "r"(b0), "r"(b1))

// ---------------------------------------------------------------------------
// GEMM core: C(128x128 fp32) = sum_k (Ah+Al)(Bh+Bl)^T via 3-pass bf16 HMMA.
// Stage = K=64 (64KB): A panels at +0,+16384; B panels at +32768,+49152.
// Panel row = 128B [hi 32k | lo 32k], XOR swizzle. 3 stages (192KB), cutlass-
// style multistage: 1 barrier per 64-K stage. 512 threads, warp tile 32x32.
// ---------------------------------------------------------------------------
#define NTH 512
#define STG    65536
#define SMEM_BYTES (3 * STG)

struct Frag {
    uint32_t aH[2][4], aL[2][4], bH[2][4], bL[2][4];
};

__device__ __forceinline__ void issue_stage(uint32_t sb, int s, int tid,
    const bf16* __restrict__ Ah, const bf16* __restrict__ Al, size_t lda,
    const bf16* __restrict__ Bh, const bf16* __restrict__ Bl, size_t ldb, int kc)
{
    const uint32_t base = sb + (uint32_t)(s % 3) * STG;
    #pragma unroll
    for (int panel = 0; panel < 2; panel++) {
        const int kcp = kc + panel * 32;
        const uint32_t pb = base + (uint32_t)panel * 16384;
        #pragma unroll
        for (int j = 0; j < 2; j++) {
            const int q   = tid + j * NTH;       // 0..1023
            const int row = q >> 3;
            const int c   = q & 7;               // chunk: 0-3 hi, 4-7 lo
            const uint32_t off = (uint32_t)(row * 128) + ((uint32_t)(c ^ (row & 7)) << 4);
            const bf16* sa = (c < 4) ? Ah + (size_t)row * lda + kcp + c * 8
                                     : Al + (size_t)row * lda + kcp + (c - 4) * 8;
            const bf16* sbp = (c < 4) ? Bh + (size_t)row * ldb + kcp + c * 8
                                      : Bl + (size_t)row * ldb + kcp + (c - 4) * 8;
            cpa16(pb + off, sa);
            cpa16(pb + 32768 + off, sbp);
        }
    }
    CP_COMMIT();
}

// kk = 0..3 within a 64-K stage: panel = kk>>1, half = kk&1
__device__ __forceinline__ void load_frags(uint32_t stage, int kk, int m0, int n0,
                                           int lane, Frag& f)
{
    const uint32_t base = stage + (uint32_t)(kk >> 1) * 16384;
    const int cb = (kk & 1) * 2;
    const int rA = lane & 15, cA = lane >> 4;
    const int rB = (lane & 7) + ((lane >> 4) << 3), cB = (lane >> 3) & 1;
    #pragma unroll
    for (int mt = 0; mt < 2; mt++) {
        const uint32_t rowb = base + (uint32_t)((m0 + mt * 16 + rA) * 128);
        LDSM4(f.aH[mt], rowb + ((uint32_t)((cb + cA)     ^ (rA & 7)) << 4));
        LDSM4(f.aL[mt], rowb + ((uint32_t)((cb + 4 + cA) ^ (rA & 7)) << 4));
    }
    #pragma unroll
    for (int nt2 = 0; nt2 < 2; nt2++) {
        const uint32_t rowb = base + 32768 + (uint32_t)((n0 + nt2 * 16 + rB) * 128);
        LDSM4(f.bH[nt2], rowb + ((uint32_t)((cb + cB)     ^ (rB & 7)) << 4));
        LDSM4(f.bL[nt2], rowb + ((uint32_t)((cb + 4 + cB) ^ (rB & 7)) << 4));
    }
}

__device__ __forceinline__ void do_mmas(const Frag& f, float acc[2][4][4]) {
    // pass-major: 8 independent accumulators between reuses
    #pragma unroll
    for (int mt = 0; mt < 2; mt++)
        #pragma unroll
        for (int nt = 0; nt < 4; nt++) {
            const int g = nt >> 1, o = (nt & 1) * 2;
            MMA(acc[mt][nt], f.aH[mt], f.bH[g][o], f.bH[g][o + 1]);
        }
    #pragma unroll
    for (int mt = 0; mt < 2; mt++)
        #pragma unroll
        for (int nt = 0; nt < 4; nt++) {
            const int g = nt >> 1, o = (nt & 1) * 2;
            MMA(acc[mt][nt], f.aH[mt], f.bL[g][o], f.bL[g][o + 1]);
        }
    #pragma unroll
    for (int mt = 0; mt < 2; mt++)
        #pragma unroll
        for (int nt = 0; nt < 4; nt++) {
            const int g = nt >> 1, o = (nt & 1) * 2;
            MMA(acc[mt][nt], f.aL[mt], f.bH[g][o], f.bH[g][o + 1]);
        }
}

// nk = K / 64, nk >= 2
__device__ __forceinline__ void run_gemm(uint32_t sb, int tid,
    const bf16* __restrict__ Ah, const bf16* __restrict__ Al, size_t lda,
    const bf16* __restrict__ Bh, const bf16* __restrict__ Bl, size_t ldb, int nk,
    float acc[2][4][4])
{
    #pragma unroll
    for (int mt = 0; mt < 2; mt++)
        #pragma unroll
        for (int nt = 0; nt < 4; nt++)
            #pragma unroll
            for (int i = 0; i < 4; i++) acc[mt][nt][i] = 0.f;

    // prologue: fill stages 0,1 (buffer 2 left empty)
    issue_stage(sb, 0, tid, Ah, Al, lda, Bh, Bl, ldb, 0);
    issue_stage(sb, 1, tid, Ah, Al, lda, Bh, Bl, ldb, 64);

    const int wid = tid >> 5, lane = tid & 31;
    const int m0 = (wid & 3) * 32, n0 = (wid >> 2) * 32;

    CP_WAIT1();                 // stage 0 resident
    __syncthreads();

    Frag fa, fb;
    load_frags(sb, 0, m0, n0, lane, fa);   // stage 0, kk=0

    for (int kt = 0; kt < nk; kt++) {
        const uint32_t cur = sb + (uint32_t)(kt % 3) * STG;
        // refill buffer (kt+2)%3 — freed at end of stage kt-1, safe after the
        // barrier that ended the previous iteration
        if (kt + 2 < nk)
            issue_stage(sb, kt + 2, tid, Ah, Al, lda, Bh, Bl, ldb, (kt + 2) * 64);
        else
            CP_COMMIT();

        load_frags(cur, 1, m0, n0, lane, fb);
        do_mmas(fa, acc);
        load_frags(cur, 2, m0, n0, lane, fa);
        do_mmas(fb, acc);
        load_frags(cur, 3, m0, n0, lane, fb);
        do_mmas(fa, acc);

        CP_WAIT1();             // stage kt+1 resident
        __syncthreads();        // ... and visible; also: all warps done with cur

        const int pkt = (kt + 1 < nk) ? kt + 1 : kt;
        load_frags(sb + (uint32_t)(pkt % 3) * STG, 0, m0, n0, lane, fa);
        do_mmas(fb, acc);
    }
}

__device__ __forceinline__ uint32_t packbf(float a, float b) {
    __nv_bfloat162 t = __floats2bfloat162_rn(a, b);
    return *reinterpret_cast<uint32_t*>(&t);
}

// ---------------------------------------------------------------------------
// GEMM 1: proj = relu(x @ W^T + b) -> split bf16
// ---------------------------------------------------------------------------
__global__ __launch_bounds__(NTH, 1) void proj_gemm(const float* __restrict__ bias) {
    extern __shared__ char smem[];
    const uint32_t sb = smem_u32(smem);
    const int tid = threadIdx.x;
    const int mblk = blockIdx.y * 128, nblk = blockIdx.x * 128;

    float acc[2][4][4];
    run_gemm(sb, tid,
             g_xh + (size_t)mblk * DDIM, g_xl + (size_t)mblk * DDIM, DDIM,
             g_wh + (size_t)nblk * DDIM, g_wl + (size_t)nblk * DDIM, DDIM,
             DDIM / 64, acc);

    const int wid = tid >> 5, lane = tid & 31;
    const int m0 = (wid & 3) * 32, n0 = (wid >> 2) * 32;
    const int quad = lane >> 2, tq = lane & 3;

    #pragma unroll
    for (int mt = 0; mt < 2; mt++)
        #pragma unroll
        for (int nt = 0; nt < 4; nt++) {
            const int col = nblk + n0 + nt * 8 + tq * 2;
            const float b0 = bias[col], b1 = bias[col + 1];
            #pragma unroll
            for (int h = 0; h < 2; h++) {
                const int row = mblk + m0 + mt * 16 + quad + h * 8;
                float v0 = fmaxf(acc[mt][nt][h * 2 + 0] + b0, 0.f);
                float v1 = fmaxf(acc[mt][nt][h * 2 + 1] + b1, 0.f);
                bf16 h0 = __float2bfloat16(v0), h1 = __float2bfloat16(v1);
                float l0 = v0 - __bfloat162float(h0), l1 = v1 - __bfloat162float(h1);
                *reinterpret_cast<uint32_t*>(g_ph + (size_t)row * DDIM + col) =
                    packbf(__bfloat162float(h0), __bfloat162float(h1));
                *reinterpret_cast<uint32_t*>(g_pl + (size_t)row * DDIM + col) =
                    packbf(l0, l1);
            }
        }
}

// ---------------------------------------------------------------------------
// GEMM 2 (symmetric): for tile pairs ti<=tj compute P_ti @ P_tj^T once,
// write tile + mirrored tile via smem transpose. diag->0, masked key -> -inf.
// ---------------------------------------------------------------------------
__global__ __launch_bounds__(NTH, 1) void scores_gemm(const int* __restrict__ x_mask) {
    extern __shared__ char smem[];
    const uint32_t sb = smem_u32(smem);
    const int tid = threadIdx.x;
    const int b = blockIdx.y;
    int p = blockIdx.x;
    int ti = 0;
    while (p >= 16 - ti) { p -= 16 - ti; ti++; }
    const int tj = ti + p;
    const size_t pb = (size_t)b * LSEQ * DDIM;

    float acc[2][4][4];
    run_gemm(sb, tid,
             g_ph + pb + (size_t)ti * 128 * DDIM, g_pl + pb + (size_t)ti * 128 * DDIM, DDIM,
             g_ph + pb + (size_t)tj * 128 * DDIM, g_pl + pb + (size_t)tj * 128 * DDIM, DDIM,
             DDIM / 64, acc);

    // ---- stage tile into smem (reuse pipeline smem) ----
    __syncthreads();
    float (*sS)[129] = reinterpret_cast<float(*)[129]>(smem);
    int* smi = reinterpret_cast<int*>(smem + 128 * 129 * 4);        // 66048
    int* smj = smi + 128;

    const int wid = tid >> 5, lane = tid & 31;
    const int m0 = (wid & 3) * 32, n0 = (wid >> 2) * 32;
    const int quad = lane >> 2, tq = lane & 3;
    const int* mk = x_mask + (size_t)b * LSEQ;

    #pragma unroll
    for (int mt = 0; mt < 2; mt++)
        #pragma unroll
        for (int nt = 0; nt < 4; nt++) {
            const int c = n0 + nt * 8 + tq * 2;
            #pragma unroll
            for (int h = 0; h < 2; h++) {
                const int r = m0 + mt * 16 + quad + h * 8;
                sS[r][c]     = acc[mt][nt][h * 2 + 0];
                sS[r][c + 1] = acc[mt][nt][h * 2 + 1];
            }
        }
    if (tid < 128) { smi[tid] = mk[ti * 128 + tid]; smj[tid] = mk[tj * 128 + tid]; }
    __syncthreads();

    float* S = g_scores + (size_t)b * LSEQ * LSEQ;
    const float NEGINF = -INFINITY;
    const int r  = tid & 127;
    const int c0 = (tid >> 7) * 32;

    // normal tile: row gi = ti*128+r, cols tj*128 + c
    {
        float* Srow = S + (size_t)(ti * 128 + r) * LSEQ + tj * 128;
        #pragma unroll
        for (int cc = 0; cc < 32; cc += 4) {
            const int c = c0 + cc;
            float4 v;
            float x0 = sS[r][c],     x1 = sS[r][c + 1];
            float x2 = sS[r][c + 2], x3 = sS[r][c + 3];
            if (ti == tj) {
                if (r == c)     x0 = 0.f;
                if (r == c + 1) x1 = 0.f;
                if (r == c + 2) x2 = 0.f;
                if (r == c + 3) x3 = 0.f;
            }
            v.x = smj[c]     ? NEGINF : x0;
            v.y = smj[c + 1] ? NEGINF : x1;
            v.z = smj[c + 2] ? NEGINF : x2;
            v.w = smj[c + 3] ? NEGINF : x3;
            *reinterpret_cast<float4*>(Srow + c) = v;
        }
    }
    // mirror tile (ti != tj): row gj = tj*128+r, cols ti*128 + c, value sS[c][r]
    if (ti != tj) {
        float* Mrow = S + (size_t)(tj * 128 + r) * LSEQ + ti * 128;
        #pragma unroll
        for (int cc = 0; cc < 32; cc += 4) {
            const int c = c0 + cc;
            float4 v;
            v.x = smi[c]     ? NEGINF : sS[c][r];
            v.y = smi[c + 1] ? NEGINF : sS[c + 1][r];
            v.z = smi[c + 2] ? NEGINF : sS[c + 2][r];
            v.w = smi[c + 3] ? NEGINF : sS[c + 3][r];
            *reinterpret_cast<float4*>(Mrow + c) = v;
        }
    }
}

// ---------------------------------------------------------------------------
// GEMM 3: out = alpha @ x   (A = alpha split, B = x^T split)
// ---------------------------------------------------------------------------
__global__ __launch_bounds__(NTH, 1) void av_gemm(float* __restrict__ out) {
    extern __shared__ char smem[];
    const uint32_t sb = smem_u32(smem);
    const int tid = threadIdx.x;
    const int b = blockIdx.z;
    const int mblk = blockIdx.y * 128, nblk = blockIdx.x * 128;

    float acc[2][4][4];
    run_gemm(sb, tid,
             g_ah + ((size_t)b * LSEQ + mblk) * LSEQ, g_al + ((size_t)b * LSEQ + mblk) * LSEQ, LSEQ,
             g_xth + ((size_t)b * DDIM + nblk) * LSEQ, g_xtl + ((size_t)b * DDIM + nblk) * LSEQ, LSEQ,
             LSEQ / 64, acc);

    const int wid = tid >> 5, lane = tid & 31;
    const int m0 = (wid & 3) * 32, n0 = (wid >> 2) * 32;
    const int quad = lane >> 2, tq = lane & 3;

    #pragma unroll
    for (int mt = 0; mt < 2; mt++)
        #pragma unroll
        for (int nt = 0; nt < 4; nt++) {
            const int col = nblk + n0 + nt * 8 + tq * 2;
            #pragma unroll
            for (int h = 0; h < 2; h++) {
                const int row = mblk + m0 + mt * 16 + quad + h * 8;
                float2 o;
                o.x = acc[mt][nt][h * 2 + 0];
                o.y = acc[mt][nt][h * 2 + 1];
                *reinterpret_cast<float2*>(out + ((size_t)b * LSEQ + row) * DDIM + col) = o;
            }
        }
}

// ---------------------------------------------------------------------------
// Softmax over keys (fp32 scores in, split-bf16 alpha out)
// ---------------------------------------------------------------------------
__global__ __launch_bounds__(256) void softmax_kernel() {
    const size_t row = blockIdx.x;
    const float* p = g_scores + row * LSEQ;
    const int t = threadIdx.x;

    float4 v0 = reinterpret_cast<const float4*>(p)[t * 2];
    float4 v1 = reinterpret_cast<const float4*>(p)[t * 2 + 1];

    float m = fmaxf(fmaxf(fmaxf(v0.x, v0.y), fmaxf(v0.z, v0.w)),
                    fmaxf(fmaxf(v1.x, v1.y), fmaxf(v1.z, v1.w)));

    __shared__ float red[8];
    #pragma unroll
    for (int off = 16; off > 0; off >>= 1)
        m = fmaxf(m, __shfl_xor_sync(0xffffffffu, m, off));
    if ((t & 31) == 0) red[t >> 5] = m;
    __syncthreads();
    if (t == 0) {
        float mm = red[0];
        #pragma unroll
        for (int w = 1; w < 8; w++) mm = fmaxf(mm, red[w]);
        red[0] = mm;
    }
    __syncthreads();
    m = red[0];
    __syncthreads();

    float e[8];
    e[0] = expf(v0.x - m); e[1] = expf(v0.y - m); e[2] = expf(v0.z - m); e[3] = expf(v0.w - m);
    e[4] = expf(v1.x - m); e[5] = expf(v1.y - m); e[6] = expf(v1.z - m); e[7] = expf(v1.w - m);
    float s = e[0] + e[1] + e[2] + e[3] + e[4] + e[5] + e[6] + e[7];
    #pragma unroll
    for (int off = 16; off > 0; off >>= 1)
        s += __shfl_xor_sync(0xffffffffu, s, off);
    if ((t & 31) == 0) red[t >> 5] = s;
    __syncthreads();
    if (t == 0) {
        float ss = 0.f;
        #pragma unroll
        for (int w = 0; w < 8; w++) ss += red[w];
        red[0] = ss;
    }
    __syncthreads();
    const float inv = 1.0f / red[0];

    uint32_t hh[4], ll[4];
    #pragma unroll
    for (int i = 0; i < 4; i++) {
        float a0 = e[2 * i] * inv, a1 = e[2 * i + 1] * inv;
        bf16 h0 = __float2bfloat16(a0), h1 = __float2bfloat16(a1);
        hh[i] = packbf(__bfloat162float(h0), __bfloat162float(h1));
        ll[i] = packbf(a0 - __bfloat162float(h0), a1 - __bfloat162float(h1));
    }
    *reinterpret_cast<uint4*>(g_ah + row * LSEQ + t * 8) = *reinterpret_cast<uint4*>(hh);
    *reinterpret_cast<uint4*>(g_al + row * LSEQ + t * 8) = *reinterpret_cast<uint4*>(ll);
}

// ---------------------------------------------------------------------------
// fp32 -> split-bf16 conversions
// ---------------------------------------------------------------------------
__global__ __launch_bounds__(256) void split_kernel(const float* __restrict__ s,
                                                    bf16* __restrict__ hi,
                                                    bf16* __restrict__ lo, int n4) {
    const int i = blockIdx.x * 256 + threadIdx.x;
    if (i >= n4) return;
    float4 v = reinterpret_cast<const float4*>(s)[i];
    bf16 h0 = __float2bfloat16(v.x), h1 = __float2bfloat16(v.y);
    bf16 h2 = __float2bfloat16(v.z), h3 = __float2bfloat16(v.w);
    uint2 uh, ul;
    uh.x = packbf(__bfloat162float(h0), __bfloat162float(h1));
    uh.y = packbf(__bfloat162float(h2), __bfloat162float(h3));
    ul.x = packbf(v.x - __bfloat162float(h0), v.y - __bfloat162float(h1));
    ul.y = packbf(v.z - __bfloat162float(h2), v.w - __bfloat162float(h3));
    reinterpret_cast<uint2*>(hi)[i] = uh;
    reinterpret_cast<uint2*>(lo)[i] = ul;
}

// x[b][l][d] -> xt[b][d][l], split bf16
__global__ __launch_bounds__(256) void transpose_split_kernel(const float* __restrict__ x) {
    __shared__ float t[32][33];
    const int b = blockIdx.z, d0 = blockIdx.x * 32, l0 = blockIdx.y * 32;
    const int tx = threadIdx.x & 31, ty = threadIdx.x >> 5;   // 32 x 8
    const float* xb = x + (size_t)b * LSEQ * DDIM;
    #pragma unroll
    for (int j = 0; j < 4; j++)
        t[ty + j * 8][tx] = xb[(size_t)(l0 + ty + j * 8) * DDIM + d0 + tx];
    __syncthreads();
    bf16* oh = g_xth + (size_t)b * DDIM * LSEQ;
    bf16* ol = g_xtl + (size_t)b * DDIM * LSEQ;
    #pragma unroll
    for (int j = 0; j < 4; j++) {
        float v = t[tx][ty + j * 8];
        bf16 h = __float2bfloat16(v);
        float lo = v - __bfloat162float(h);
        const size_t o = (size_t)(d0 + ty + j * 8) * LSEQ + l0 + tx;
        oh[o] = h;
        ol[o] = __float2bfloat16(lo);
    }
}

// ---------------------------------------------------------------------------
extern "C" void kernel_launch(void* const* d_in, const int* in_sizes, int n_in,
                              void* d_out, int out_size) {
    const float* x      = (const float*)d_in[0];   // [8, 2048, 1024]
    const int*   x_mask = (const int*)d_in[1];     // [8, 2048]
    const float* W      = (const float*)d_in[2];   // [1024, 1024]
    const float* bias   = (const float*)d_in[3];   // [1024]
    float* out = (float*)d_out;                    // [8, 2048, 1024]

    cudaFuncSetAttribute(proj_gemm,   cudaFuncAttributeMaxDynamicSharedMemorySize, SMEM_BYTES);
    cudaFuncSetAttribute(scores_gemm, cudaFuncAttributeMaxDynamicSharedMemorySize, SMEM_BYTES);
    cudaFuncSetAttribute(av_gemm,     cudaFuncAttributeMaxDynamicSharedMemorySize, SMEM_BYTES);

    bf16 *xh, *xl, *wh, *wl;
    cudaGetSymbolAddress((void**)&xh, g_xh);
    cudaGetSymbolAddress((void**)&xl, g_xl);
    cudaGetSymbolAddress((void**)&wh, g_wh);
    cudaGetSymbolAddress((void**)&wl, g_wl);

    const int nx4 = BATCH * LSEQ * DDIM / 4;
    const int nw4 = DDIM * DDIM / 4;

    split_kernel<<<(nx4 + 255) / 256, 256>>>(x, xh, xl, nx4);
    split_kernel<<<(nw4 + 255) / 256, 256>>>(W, wh, wl, nw4);
    transpose_split_kernel<<<dim3(DDIM / 32, LSEQ / 32, BATCH), 256>>>(x);

    proj_gemm  <<<dim3(DDIM / 128, (BATCH * LSEQ) / 128), NTH, SMEM_BYTES>>>(bias);
    scores_gemm<<<dim3(136, BATCH), NTH, SMEM_BYTES>>>(x_mask);
    softmax_kernel<<<BATCH * LSEQ, 256>>>();
    av_gemm    <<<dim3(DDIM / 128, LSEQ / 128, BATCH), NTH, SMEM_BYTES>>>(out);
}